// round 11
// baseline (speedup 1.0000x reference)
#include <cuda_runtime.h>
#include <math.h>

// ---------------------------------------------------------------------------
// VQ-VAE forward, fp32. B=16, D=256, K=512.
// VQ dot emulates XLA:CPU vectorized reduce: 8 interleaved accumulators
// (k = 8j + l), fmuladd, shuffle-halving tree combine:
//   ((a0+a4)+(a2+a6)) + ((a1+a5)+(a3+a7)).
// Score: s_k = fl(fl(zsq+esq_k) - fl(2*dot_k)); ties -> lowest index.
// Output: [x_recon 3145728][z_e 16777216][z_q 16777216][perp 1]
// ---------------------------------------------------------------------------

#define OFF_ZE   3145728
#define OFF_ZQ   19922944
#define OFF_PERP 36700160

// ------------------------- scratch (device globals) -----------------------
__device__ float g_h1[16 * 64 * 128 * 128];
__device__ float g_h2[16 * 128 * 64 * 64];
__device__ float g_zq_nchw[16 * 256 * 64 * 64];
__device__ float g_d1[16 * 128 * 128 * 128];
__device__ float g_d2[16 * 64 * 256 * 256];
__device__ float g_wt_post[4 * 128 * 256 * 4];
__device__ float g_wt_dec1[4 * 64 * 128 * 4];
__device__ float g_wc1[64 * 48];
__device__ float g_wc2[128 * 1024];
__device__ float g_wc3[256 * 1152];
__device__ float g_esq[512];
__device__ int   g_counts[512];

// Repack conv weights w(Cout,Cin,KS,KS) -> wr[co][(kw*KS+kh)*Cin + ci]
template <int Cin, int Cout, int KS>
__global__ void repack_conv(const float* __restrict__ w, float* __restrict__ wr)
{
    int idx = blockIdx.x * 256 + threadIdx.x;
    if (idx >= Cout * Cin * KS * KS) return;
    int ci = idx % Cin;
    int t  = idx / Cin;
    int kh = t % KS;
    int t2 = t / KS;
    int kw = t2 % KS;
    int co = t2 / KS;
    wr[idx] = w[((co * Cin + ci) * KS + kh) * KS + kw];
}

// --------------------- implicit-GEMM conv (fp32) ---------------------------
template <int Cin, int Cout, int KS, int S, int P,
          int Hin, int Win, int Hout, int Wout, bool RELU, bool NHWC_OUT>
__global__ void __launch_bounds__(256)
conv_gemm(const float* __restrict__ in, const float* __restrict__ w,
          const float* __restrict__ bias, float* __restrict__ out)
{
    constexpr int KK   = Cin * KS * KS;
    constexpr int Npix = Hout * Wout;

    __shared__ float As[16][64];
    __shared__ float Bs[16][64];

    const int t  = threadIdx.x;
    const int n0 = blockIdx.x * 64;
    const int m0 = blockIdx.y * 64;
    const int b  = blockIdx.z;
    const int tm = t >> 4;
    const int tn = t & 15;
    const int ma = t >> 2;
    const int ka = (t & 3) << 2;
    const int nb  = t & 63;
    const int kb0 = t >> 6;

    const int nglob = n0 + nb;
    const int ho_b  = nglob / Wout;
    const int wo_b  = nglob - ho_b * Wout;
    const float* inb = in + (size_t)b * Cin * Hin * Win;

    float acc[4][4];
#pragma unroll
    for (int i = 0; i < 4; i++)
#pragma unroll
        for (int j = 0; j < 4; j++) acc[i][j] = 0.f;

    for (int kb = 0; kb < KK; kb += 16) {
        float4 av = *(const float4*)(w + (size_t)(m0 + ma) * KK + kb + ka);
        float bv[4];
#pragma unroll
        for (int j = 0; j < 4; j++) {
            int kk = kb + kb0 + 4 * j;
            int ci = kk % Cin;
            int r  = kk / Cin;
            int kh = r % KS;
            int kw = r / KS;
            int hi = ho_b * S - P + kh;
            int wi = wo_b * S - P + kw;
            float v = 0.f;
            if (hi >= 0 && hi < Hin && wi >= 0 && wi < Win)
                v = inb[(ci * Hin + hi) * Win + wi];
            bv[j] = v;
        }
        __syncthreads();
        As[ka + 0][ma] = av.x; As[ka + 1][ma] = av.y;
        As[ka + 2][ma] = av.z; As[ka + 3][ma] = av.w;
#pragma unroll
        for (int j = 0; j < 4; j++) Bs[kb0 + 4 * j][nb] = bv[j];
        __syncthreads();

#pragma unroll
        for (int k = 0; k < 16; k++) {
            float4 a  = *(const float4*)&As[k][tm * 4];
            float4 bq = *(const float4*)&Bs[k][tn * 4];
            float ar[4] = {a.x, a.y, a.z, a.w};
            float br[4] = {bq.x, bq.y, bq.z, bq.w};
#pragma unroll
            for (int i = 0; i < 4; i++)
#pragma unroll
                for (int j = 0; j < 4; j++) acc[i][j] += ar[i] * br[j];
        }
    }

#pragma unroll
    for (int i = 0; i < 4; i++) {
        int m = m0 + tm * 4 + i;
        float bb = bias[m];
#pragma unroll
        for (int j = 0; j < 4; j++) {
            float v = acc[i][j] + bb;
            if (RELU) v = fmaxf(v, 0.f);
            int n = n0 + tn * 4 + j;
            if (NHWC_OUT)
                out[((size_t)b * Npix + n) * Cout + m] = v;
            else
                out[((size_t)b * Cout + m) * Npix + n] = v;
        }
    }
}

// --------------------- convT s=2 k=4 p=1 (fp32) ----------------------------
template <int Cin, int Cout, int Hin, int Win, bool RELU>
__global__ void __launch_bounds__(256)
tconv_gemm(const float* __restrict__ in, const float* __restrict__ wt,
           const float* __restrict__ bias, float* __restrict__ out)
{
    constexpr int KK   = Cin * 4;
    constexpr int Hout = Hin * 2;
    constexpr int Wout = Win * 2;

    __shared__ float As[16][64];
    __shared__ float Bs[16][64];

    const int t    = threadIdx.x;
    const int n0   = blockIdx.x * 64;
    const int mcls = blockIdx.y;
    const int m0   = (mcls >> 2) * 64;
    const int cls  = mcls & 3;
    const int ph   = cls >> 1;
    const int pw   = cls & 1;
    const int b    = blockIdx.z;
    const int tm   = t >> 4;
    const int tn   = t & 15;
    const int ma  = t >> 2;
    const int ka  = (t & 3) << 2;
    const int nb  = t & 63;
    const int kb0 = t >> 6;

    const int nglob = n0 + nb;
    const int oy = nglob / Win;
    const int ox = nglob - oy * Win;
    const float* inb  = in + (size_t)b * Cin * Hin * Win;
    const float* wcls = wt + (size_t)cls * Cout * KK;

    float acc[4][4];
#pragma unroll
    for (int i = 0; i < 4; i++)
#pragma unroll
        for (int j = 0; j < 4; j++) acc[i][j] = 0.f;

    for (int kb = 0; kb < KK; kb += 16) {
        float4 av = *(const float4*)(wcls + (size_t)(m0 + ma) * KK + kb + ka);
        float bv[4];
#pragma unroll
        for (int j = 0; j < 4; j++) {
            int kk = kb + kb0 + 4 * j;
            int ci = kk >> 2;
            int tt = kk & 3;
            int ty = tt >> 1;
            int tx = tt & 1;
            int hi = oy + ph - ty;
            int wi = ox + pw - tx;
            float v = 0.f;
            if (hi >= 0 && hi < Hin && wi >= 0 && wi < Win)
                v = inb[(ci * Hin + hi) * Win + wi];
            bv[j] = v;
        }
        __syncthreads();
        As[ka + 0][ma] = av.x; As[ka + 1][ma] = av.y;
        As[ka + 2][ma] = av.z; As[ka + 3][ma] = av.w;
#pragma unroll
        for (int j = 0; j < 4; j++) Bs[kb0 + 4 * j][nb] = bv[j];
        __syncthreads();

#pragma unroll
        for (int k = 0; k < 16; k++) {
            float4 a  = *(const float4*)&As[k][tm * 4];
            float4 bq = *(const float4*)&Bs[k][tn * 4];
            float ar[4] = {a.x, a.y, a.z, a.w};
            float br[4] = {bq.x, bq.y, bq.z, bq.w};
#pragma unroll
            for (int i = 0; i < 4; i++)
#pragma unroll
                for (int j = 0; j < 4; j++) acc[i][j] += ar[i] * br[j];
        }
    }

#pragma unroll
    for (int i = 0; i < 4; i++) {
        int m = m0 + tm * 4 + i;
        float bb = bias[m];
#pragma unroll
        for (int j = 0; j < 4; j++) {
            float v = acc[i][j] + bb;
            if (RELU) v = fmaxf(v, 0.f);
            int n  = n0 + tn * 4 + j;
            int yy = n / Win;
            int xx = n - yy * Win;
            int ho = 2 * yy + ph;
            int wo = 2 * xx + pw;
            out[(((size_t)b * Cout + m) * Hout + ho) * Wout + wo] = v;
        }
    }
}

template <int Cin, int Cout>
__global__ void repack_tconv(const float* __restrict__ w, float* __restrict__ wt)
{
    int idx = blockIdx.x * 256 + threadIdx.x;
    if (idx >= Cin * Cout * 16) return;
    int tt  = idx & 3;
    int t2  = idx >> 2;
    int ci  = t2 % Cin;
    int t3  = t2 / Cin;
    int co  = t3 % Cout;
    int cls = t3 / Cout;
    int ph = cls >> 1, pw = cls & 1;
    int ty = tt >> 1,  tx = tt & 1;
    int kh = ph ? (ty ? 2 : 0) : (ty ? 3 : 1);
    int kw = pw ? (tx ? 2 : 0) : (tx ? 3 : 1);
    wt[idx] = w[((ci * Cout + co) * 4 + kh) * 4 + kw];
}

__global__ void __launch_bounds__(256)
dec2_kernel(const float* __restrict__ in, const float* __restrict__ w,
            const float* __restrict__ bias, float* __restrict__ out)
{
    __shared__ float ws[3 * 64 * 9];
    for (int i = threadIdx.x; i < 3 * 64 * 9; i += 256) {
        int q  = i % 9;
        int ci = (i / 9) % 64;
        int co = i / (9 * 64);
        int kh = q / 3, kw = q % 3;
        ws[i] = w[((ci * 3 + co) * 3 + (2 - kh)) * 3 + (2 - kw)];
    }
    __syncthreads();

    int pix = blockIdx.x * 256 + threadIdx.x;
    int b  = pix >> 16;
    int p  = pix & 65535;
    int ho = p >> 8;
    int wo = p & 255;
    float a0 = bias[0], a1 = bias[1], a2 = bias[2];
    const float* inb = in + (size_t)b * 64 * 65536;
    for (int ci = 0; ci < 64; ci++) {
        float r[9];
#pragma unroll
        for (int kh = 0; kh < 3; kh++)
#pragma unroll
            for (int kw = 0; kw < 3; kw++) {
                int hi = ho - 1 + kh, wi = wo - 1 + kw;
                r[kh * 3 + kw] = (hi >= 0 && hi < 256 && wi >= 0 && wi < 256)
                                     ? inb[ci * 65536 + hi * 256 + wi] : 0.f;
            }
#pragma unroll
        for (int q = 0; q < 9; q++) {
            a0 += r[q] * ws[0 * 576 + ci * 9 + q];
            a1 += r[q] * ws[1 * 576 + ci * 9 + q];
            a2 += r[q] * ws[2 * 576 + ci * 9 + q];
        }
    }
    out[(b * 3 + 0) * 65536 + p] = a0;
    out[(b * 3 + 1) * 65536 + p] = a1;
    out[(b * 3 + 2) * 65536 + p] = a2;
}

// ------------------------------- VQ ---------------------------------------
__global__ void zero_counts_kernel() { g_counts[threadIdx.x] = 0; }

__global__ void esq_kernel(const float* __restrict__ emb)
{
    int k = blockIdx.x * 128 + threadIdx.x;
    if (k < 512) {
        const float4* e = (const float4*)(emb + (size_t)k * 256);
        float s = 0.f;
#pragma unroll
        for (int i = 0; i < 64; i++) {
            float4 v = e[i];
            s += v.x * v.x + v.y * v.y + v.z * v.z + v.w * v.w;
        }
        g_esq[k] = s;
    }
}

__global__ void __launch_bounds__(256)
vq_kernel(const float* __restrict__ ze, const float* __restrict__ emb,
          float* __restrict__ zq_nhwc, float* __restrict__ zq_nchw)
{
    __shared__ float Zs[256][32];
    __shared__ float Es[32][64];
    __shared__ float zpart[32][8];
    __shared__ float zsqs[32];
    __shared__ float rbest[32][16];
    __shared__ int   rk[32][16];
    __shared__ int   fidx[32];

    const int t  = threadIdx.x;
    const int n0 = blockIdx.x * 32;
    const int tm = t >> 4;
    const int tn = t & 15;
    const int r0 = tm * 2, r1 = tm * 2 + 1;

#pragma unroll
    for (int j = 0; j < 8; j++) {
        int idx = t + 256 * j;
        int m   = idx >> 6;
        int kq  = idx & 63;
        float4 v = *(const float4*)(ze + ((size_t)(n0 + m)) * 256 + kq * 4);
        Zs[kq * 4 + 0][m] = v.x; Zs[kq * 4 + 1][m] = v.y;
        Zs[kq * 4 + 2][m] = v.z; Zs[kq * 4 + 3][m] = v.w;
    }
    __syncthreads();

    {   // per-row |z|^2 fp32 (argmin-irrelevant by uniform-shift lemma)
        int row = t & 31;
        int seg = t >> 5;
        float s = 0.f;
#pragma unroll
        for (int i = 0; i < 32; i++) {
            float v = Zs[seg * 32 + i][row];
            s += v * v;
        }
        zpart[row][seg] = s;
    }
    __syncthreads();
    if (t < 32) {
        float s = zpart[t][0];
#pragma unroll
        for (int q = 1; q < 8; q++) s += zpart[t][q];
        zsqs[t] = s;
    }
    __syncthreads();

    const float zr0 = zsqs[r0];
    const float zr1 = zsqs[r1];

    float best[2] = {1e30f, 1e30f};
    int   bk[2]   = {0, 0};

    for (int e0 = 0; e0 < 512; e0 += 64) {
        // 8 interleaved accumulators per (row, code): acc[l] takes k = 8j+l
        float acc[8][2][2];   // [lane][row][code-pair half]
        float acc2[8][2][2];  // second pair of codes
#pragma unroll
        for (int l = 0; l < 8; l++)
#pragma unroll
            for (int i = 0; i < 2; i++)
#pragma unroll
                for (int j = 0; j < 2; j++) { acc[l][i][j] = 0.f; acc2[l][i][j] = 0.f; }

        for (int kb = 0; kb < 256; kb += 32) {
            __syncthreads();
#pragma unroll
            for (int j = 0; j < 2; j++) {
                int idx = t + 256 * j;
                int e   = idx >> 3;
                int k4  = (idx & 7) * 4;
                float4 v = *(const float4*)(emb + (size_t)(e0 + e) * 256 + kb + k4);
                Es[k4 + 0][e] = v.x; Es[k4 + 1][e] = v.y;
                Es[k4 + 2][e] = v.z; Es[k4 + 3][e] = v.w;
            }
            __syncthreads();
#pragma unroll
            for (int k = 0; k < 32; k++) {
                const int l = k & 7;   // global (kb+k) & 7 since kb % 8 == 0
                float a0 = Zs[kb + k][r0];
                float a1 = Zs[kb + k][r1];
                float4 bq = *(const float4*)&Es[k][tn * 4];
                acc [l][0][0] = __fmaf_rn(a0, bq.x, acc [l][0][0]);
                acc [l][0][1] = __fmaf_rn(a0, bq.y, acc [l][0][1]);
                acc2[l][0][0] = __fmaf_rn(a0, bq.z, acc2[l][0][0]);
                acc2[l][0][1] = __fmaf_rn(a0, bq.w, acc2[l][0][1]);
                acc [l][1][0] = __fmaf_rn(a1, bq.x, acc [l][1][0]);
                acc [l][1][1] = __fmaf_rn(a1, bq.y, acc [l][1][1]);
                acc2[l][1][0] = __fmaf_rn(a1, bq.z, acc2[l][1][0]);
                acc2[l][1][1] = __fmaf_rn(a1, bq.w, acc2[l][1][1]);
            }
        }
        // LLVM shuffle-halving combine: ((a0+a4)+(a2+a6)) + ((a1+a5)+(a3+a7))
#pragma unroll
        for (int i = 0; i < 2; i++) {
            float zr = (i == 0) ? zr0 : zr1;
#pragma unroll
            for (int j = 0; j < 4; j++) {
                float d;
                if (j < 2) {
                    float q0 = __fadd_rn(acc[0][i][j], acc[4][i][j]);
                    float q1 = __fadd_rn(acc[1][i][j], acc[5][i][j]);
                    float q2 = __fadd_rn(acc[2][i][j], acc[6][i][j]);
                    float q3 = __fadd_rn(acc[3][i][j], acc[7][i][j]);
                    d = __fadd_rn(__fadd_rn(q0, q2), __fadd_rn(q1, q3));
                } else {
                    int jj = j - 2;
                    float q0 = __fadd_rn(acc2[0][i][jj], acc2[4][i][jj]);
                    float q1 = __fadd_rn(acc2[1][i][jj], acc2[5][i][jj]);
                    float q2 = __fadd_rn(acc2[2][i][jj], acc2[6][i][jj]);
                    float q3 = __fadd_rn(acc2[3][i][jj], acc2[7][i][jj]);
                    d = __fadd_rn(__fadd_rn(q0, q2), __fadd_rn(q1, q3));
                }
                int kcode = e0 + tn * 4 + j;
                float eq = g_esq[kcode];
                float s = __fadd_rn(__fadd_rn(zr, eq), -__fmul_rn(2.f, d));
                if (s < best[i]) { best[i] = s; bk[i] = kcode; }
            }
        }
    }
    __syncthreads();
    rbest[r0][tn] = best[0]; rk[r0][tn] = bk[0];
    rbest[r1][tn] = best[1]; rk[r1][tn] = bk[1];
    __syncthreads();
    if (t < 32) {
        float bs = rbest[t][0];
        int   bi = rk[t][0];
#pragma unroll
        for (int q = 1; q < 16; q++) {
            float s = rbest[t][q];
            int   k = rk[t][q];
            if (s < bs || (s == bs && k < bi)) { bs = s; bi = k; }
        }
        fidx[t] = bi;
        atomicAdd(&g_counts[bi], 1);
    }
    __syncthreads();

    // z_q NHWC: exact codebook rows
#pragma unroll
    for (int j = 0; j < 8; j++) {
        int idx = t + 256 * j;
        int m   = idx >> 6;
        int d4  = idx & 63;
        float4 v = *(const float4*)(emb + (size_t)fidx[m] * 256 + d4 * 4);
        *(float4*)(zq_nhwc + ((size_t)(n0 + m)) * 256 + d4 * 4) = v;
    }
    // decoder input NCHW: z_e + (z_q - z_e), fp32 exact order
    {
        int lane = t & 31, wrp = t >> 5;
        int n    = n0 + lane;
        int bimg = n >> 12;
        int pixl = n & 4095;
        int code = fidx[lane];
#pragma unroll
        for (int j = 0; j < 32; j++) {
            int d = wrp + 8 * j;
            float qv  = emb[(size_t)code * 256 + d];
            float zev = Zs[d][lane];
            zq_nchw[(((size_t)bimg * 256 + d) << 12) + pixl] = zev + (qv - zev);
        }
    }
}

__global__ void perp_kernel(float* __restrict__ out)
{
    __shared__ float red[512];
    int t = threadIdx.x;
    float p = (float)g_counts[t] * (1.f / 65536.f);
    red[t] = p * logf(p + 1e-10f);
    __syncthreads();
    for (int s = 256; s > 0; s >>= 1) {
        if (t < s) red[t] += red[t + s];
        __syncthreads();
    }
    if (t == 0) out[0] = expf(-red[0]);
}

// ---------------------------------------------------------------------------
extern "C" void kernel_launch(void* const* d_in, const int* in_sizes, int n_in,
                              void* d_out, int out_size)
{
    const float* x      = (const float*)d_in[0];
    const float* w_enc1 = (const float*)d_in[1];
    const float* b_enc1 = (const float*)d_in[2];
    const float* w_enc2 = (const float*)d_in[3];
    const float* b_enc2 = (const float*)d_in[4];
    const float* w_prevq= (const float*)d_in[5];
    const float* b_prevq= (const float*)d_in[6];
    const float* emb    = (const float*)d_in[7];
    const float* w_post = (const float*)d_in[8];
    const float* b_post = (const float*)d_in[9];
    const float* w_dec1 = (const float*)d_in[10];
    const float* b_dec1 = (const float*)d_in[11];
    const float* w_dec2 = (const float*)d_in[12];
    const float* b_dec2 = (const float*)d_in[13];

    float* out  = (float*)d_out;
    float* ze   = out + OFF_ZE;
    float* zq   = out + OFF_ZQ;
    float* perp = out + OFF_PERP;

    void* p;
    cudaGetSymbolAddress(&p, g_h1);       float* h1  = (float*)p;
    cudaGetSymbolAddress(&p, g_h2);       float* h2  = (float*)p;
    cudaGetSymbolAddress(&p, g_zq_nchw);  float* zqn = (float*)p;
    cudaGetSymbolAddress(&p, g_d1);       float* d1  = (float*)p;
    cudaGetSymbolAddress(&p, g_d2);       float* d2  = (float*)p;
    cudaGetSymbolAddress(&p, g_wt_post);  float* wtp = (float*)p;
    cudaGetSymbolAddress(&p, g_wt_dec1);  float* wtd = (float*)p;
    cudaGetSymbolAddress(&p, g_wc1);      float* wc1 = (float*)p;
    cudaGetSymbolAddress(&p, g_wc2);      float* wc2 = (float*)p;
    cudaGetSymbolAddress(&p, g_wc3);      float* wc3 = (float*)p;

    zero_counts_kernel<<<1, 512>>>();
    esq_kernel<<<4, 128>>>(emb);
    repack_conv<3, 64, 4><<<12, 256>>>(w_enc1, wc1);
    repack_conv<64, 128, 4><<<512, 256>>>(w_enc2, wc2);
    repack_conv<128, 256, 3><<<1152, 256>>>(w_prevq, wc3);
    repack_tconv<256, 128><<<2048, 256>>>(w_post, wtp);
    repack_tconv<128, 64><<<512, 256>>>(w_dec1, wtd);

    conv_gemm<3, 64, 4, 2, 1, 256, 256, 128, 128, true, false>
        <<<dim3(256, 1, 16), 256>>>(x, wc1, b_enc1, h1);
    conv_gemm<64, 128, 4, 2, 1, 128, 128, 64, 64, true, false>
        <<<dim3(64, 2, 16), 256>>>(h1, wc2, b_enc2, h2);
    conv_gemm<128, 256, 3, 1, 1, 64, 64, 64, 64, false, true>
        <<<dim3(64, 4, 16), 256>>>(h2, wc3, b_prevq, ze);

    vq_kernel<<<2048, 256>>>(ze, emb, zq, zqn);
    perp_kernel<<<1, 512>>>(perp);

    tconv_gemm<256, 128, 64, 64, false>
        <<<dim3(64, 8, 16), 256>>>(zqn, wtp, b_post, d1);
    tconv_gemm<128, 64, 128, 128, true>
        <<<dim3(256, 4, 16), 256>>>(d1, wtd, b_dec1, d2);
    dec2_kernel<<<4096, 256>>>(d2, w_dec2, b_dec2, out);
}

// round 12
// speedup vs baseline: 1.2042x; 1.2042x over previous
#include <cuda_runtime.h>
#include <math.h>

// ---------------------------------------------------------------------------
// VQ-VAE forward, fp32. B=16, D=256, K=512.   PASSING NUMERICS (frozen):
//  - encoder convs: kw-major ci-fastest k-order, single ascending FMA chain
//  - VQ dot: 8 interleaved accumulators + shuffle-halving combine
//  - score s = fl(fl(zsq+esq) - fl(2*dot)), ties -> lowest index
// Perf: big GEMMs (enc2, prevq, post, dec1) use 8x8 micro-tiles with packed
// fma.rn.f32x2 (FFMA2, 2x fp32 rate, lane-wise IEEE rn => bit-identical).
// Output: [x_recon 3145728][z_e 16777216][z_q 16777216][perp 1]
// ---------------------------------------------------------------------------

#define OFF_ZE   3145728
#define OFF_ZQ   19922944
#define OFF_PERP 36700160

typedef unsigned long long u64;

__device__ __forceinline__ void ffma2(u64& acc, u64 a, u64 b)
{
    asm("fma.rn.f32x2 %0, %1, %2, %0;" : "+l"(acc) : "l"(a), "l"(b));
}
__device__ __forceinline__ u64 dup2(float x)
{
    u64 r;
    asm("mov.b64 %0, {%1, %1};" : "=l"(r) : "r"(__float_as_uint(x)));
    return r;
}
__device__ __forceinline__ void unpack2(u64 v, float& lo, float& hi)
{
    unsigned a, b;
    asm("mov.b64 {%0, %1}, %2;" : "=r"(a), "=r"(b) : "l"(v));
    lo = __uint_as_float(a); hi = __uint_as_float(b);
}
// bank-conflict gap: insert 4 floats every 32
__device__ __forceinline__ int pn(int n) { return n + ((n >> 5) << 2); }

// ------------------------- scratch (device globals) -----------------------
__device__ float g_h1[16 * 64 * 128 * 128];
__device__ float g_h2[16 * 128 * 64 * 64];
__device__ float g_zq_nchw[16 * 256 * 64 * 64];
__device__ float g_d1[16 * 128 * 128 * 128];
__device__ float g_d2[16 * 64 * 256 * 256];
__device__ float g_wt_post[4 * 128 * 256 * 4];
__device__ float g_wt_dec1[4 * 64 * 128 * 4];
__device__ float g_wc1[64 * 48];
__device__ float g_wc2[128 * 1024];
__device__ float g_wc3[256 * 1152];
__device__ float g_esq[512];
__device__ int   g_counts[512];

// Repack conv weights w(Cout,Cin,KS,KS) -> wr[co][(kw*KS+kh)*Cin + ci]
template <int Cin, int Cout, int KS>
__global__ void repack_conv(const float* __restrict__ w, float* __restrict__ wr)
{
    int idx = blockIdx.x * 256 + threadIdx.x;
    if (idx >= Cout * Cin * KS * KS) return;
    int ci = idx % Cin;
    int t  = idx / Cin;
    int kh = t % KS;
    int t2 = t / KS;
    int kw = t2 % KS;
    int co = t2 / KS;
    wr[idx] = w[((co * Cin + ci) * KS + kh) * KS + kw];
}

// --------------------- old 4x4 conv (enc1 only) ----------------------------
template <int Cin, int Cout, int KS, int S, int P,
          int Hin, int Win, int Hout, int Wout, bool RELU, bool NHWC_OUT>
__global__ void __launch_bounds__(256)
conv_gemm(const float* __restrict__ in, const float* __restrict__ w,
          const float* __restrict__ bias, float* __restrict__ out)
{
    constexpr int KK   = Cin * KS * KS;
    constexpr int Npix = Hout * Wout;

    __shared__ float As[16][64];
    __shared__ float Bs[16][64];

    const int t  = threadIdx.x;
    const int n0 = blockIdx.x * 64;
    const int m0 = blockIdx.y * 64;
    const int b  = blockIdx.z;
    const int tm = t >> 4;
    const int tn = t & 15;
    const int ma = t >> 2;
    const int ka = (t & 3) << 2;
    const int nb  = t & 63;
    const int kb0 = t >> 6;

    const int nglob = n0 + nb;
    const int ho_b  = nglob / Wout;
    const int wo_b  = nglob - ho_b * Wout;
    const float* inb = in + (size_t)b * Cin * Hin * Win;

    float acc[4][4];
#pragma unroll
    for (int i = 0; i < 4; i++)
#pragma unroll
        for (int j = 0; j < 4; j++) acc[i][j] = 0.f;

    for (int kb = 0; kb < KK; kb += 16) {
        float4 av = *(const float4*)(w + (size_t)(m0 + ma) * KK + kb + ka);
        float bv[4];
#pragma unroll
        for (int j = 0; j < 4; j++) {
            int kk = kb + kb0 + 4 * j;
            int ci = kk % Cin;
            int r  = kk / Cin;
            int kh = r % KS;
            int kw = r / KS;
            int hi = ho_b * S - P + kh;
            int wi = wo_b * S - P + kw;
            float v = 0.f;
            if (hi >= 0 && hi < Hin && wi >= 0 && wi < Win)
                v = inb[(ci * Hin + hi) * Win + wi];
            bv[j] = v;
        }
        __syncthreads();
        As[ka + 0][ma] = av.x; As[ka + 1][ma] = av.y;
        As[ka + 2][ma] = av.z; As[ka + 3][ma] = av.w;
#pragma unroll
        for (int j = 0; j < 4; j++) Bs[kb0 + 4 * j][nb] = bv[j];
        __syncthreads();

#pragma unroll
        for (int k = 0; k < 16; k++) {
            float4 a  = *(const float4*)&As[k][tm * 4];
            float4 bq = *(const float4*)&Bs[k][tn * 4];
            float ar[4] = {a.x, a.y, a.z, a.w};
            float br[4] = {bq.x, bq.y, bq.z, bq.w};
#pragma unroll
            for (int i = 0; i < 4; i++)
#pragma unroll
                for (int j = 0; j < 4; j++) acc[i][j] += ar[i] * br[j];
        }
    }

#pragma unroll
    for (int i = 0; i < 4; i++) {
        int m = m0 + tm * 4 + i;
        float bb = bias[m];
#pragma unroll
        for (int j = 0; j < 4; j++) {
            float v = acc[i][j] + bb;
            if (RELU) v = fmaxf(v, 0.f);
            int n = n0 + tn * 4 + j;
            if (NHWC_OUT)
                out[((size_t)b * Npix + n) * Cout + m] = v;
            else
                out[((size_t)b * Cout + m) * Npix + n] = v;
        }
    }
}

// --------------- 8x8 f32x2 conv (enc2, prevq): BM=128, BN=128 --------------
template <int Cin, int Cout, int KS, int S, int P,
          int Hin, int Win, int Hout, int Wout, bool RELU, bool NHWC_OUT>
__global__ void __launch_bounds__(256, 2)
conv_gemm2(const float* __restrict__ in, const float* __restrict__ w,
           const float* __restrict__ bias, float* __restrict__ out)
{
    constexpr int KK   = Cin * KS * KS;
    constexpr int Npix = Hout * Wout;

    __shared__ float As[16][128];
    __shared__ float Bs[16][144];   // 128 + gap

    const int t  = threadIdx.x;
    const int n0 = blockIdx.x * 128;
    const int m0 = blockIdx.y * 128;
    const int b  = blockIdx.z;
    const int tm = t >> 4;          // 0..15 -> 8 m each
    const int tn = t & 15;          // 0..15 -> 8 n each

    // A staging: a_m = t>>1 (0..127), a_k = (t&1)*8
    const int a_m = t >> 1;
    const int a_k = (t & 1) * 8;
    // B staging: bn = t&127, kk0 = (t>>7)*8
    const int bn  = t & 127;
    const int kk0 = (t >> 7) * 8;

    const int nglob = n0 + bn;
    const int ho_b  = nglob / Wout;
    const int wo_b  = nglob - ho_b * Wout;
    const float* inb = in + (size_t)b * Cin * Hin * Win;

    u64 acc[4][8];
#pragma unroll
    for (int p = 0; p < 4; p++)
#pragma unroll
        for (int j = 0; j < 8; j++) acc[p][j] = 0ull;

    const int pnb = pn(tn * 8);

    for (int kb = 0; kb < KK; kb += 16) {
        float4 av0 = *(const float4*)(w + (size_t)(m0 + a_m) * KK + kb + a_k);
        float4 av1 = *(const float4*)(w + (size_t)(m0 + a_m) * KK + kb + a_k + 4);
        float bv[8];
#pragma unroll
        for (int i = 0; i < 8; i++) {
            int kk = kb + kk0 + i;
            int ci = kk % Cin;
            int r  = kk / Cin;
            int kh = r % KS;
            int kw = r / KS;
            int hi = ho_b * S - P + kh;
            int wi = wo_b * S - P + kw;
            float v = 0.f;
            if (hi >= 0 && hi < Hin && wi >= 0 && wi < Win)
                v = inb[(ci * Hin + hi) * Win + wi];
            bv[i] = v;
        }
        __syncthreads();
        As[a_k + 0][a_m] = av0.x; As[a_k + 1][a_m] = av0.y;
        As[a_k + 2][a_m] = av0.z; As[a_k + 3][a_m] = av0.w;
        As[a_k + 4][a_m] = av1.x; As[a_k + 5][a_m] = av1.y;
        As[a_k + 6][a_m] = av1.z; As[a_k + 7][a_m] = av1.w;
        {
            int pb = pn(bn);
#pragma unroll
            for (int i = 0; i < 8; i++) Bs[kk0 + i][pb] = bv[i];
        }
        __syncthreads();

#pragma unroll
        for (int k = 0; k < 16; k++) {
            ulonglong2 ax = *(const ulonglong2*)&As[k][tm * 8];
            ulonglong2 ay = *(const ulonglong2*)&As[k][tm * 8 + 4];
            u64 A[4] = {ax.x, ax.y, ay.x, ay.y};
            float4 b0 = *(const float4*)&Bs[k][pnb];
            float4 b1 = *(const float4*)&Bs[k][pnb + 4];
            u64 bd[8] = {dup2(b0.x), dup2(b0.y), dup2(b0.z), dup2(b0.w),
                         dup2(b1.x), dup2(b1.y), dup2(b1.z), dup2(b1.w)};
#pragma unroll
            for (int p = 0; p < 4; p++)
#pragma unroll
                for (int j = 0; j < 8; j++) ffma2(acc[p][j], A[p], bd[j]);
        }
    }

#pragma unroll
    for (int p = 0; p < 4; p++) {
        int mlo = m0 + tm * 8 + 2 * p;
        float blo = bias[mlo], bhi = bias[mlo + 1];
#pragma unroll
        for (int j = 0; j < 8; j++) {
            float lo, hi;
            unpack2(acc[p][j], lo, hi);
            float v0 = lo + blo;
            float v1 = hi + bhi;
            if (RELU) { v0 = fmaxf(v0, 0.f); v1 = fmaxf(v1, 0.f); }
            int n = n0 + tn * 8 + j;
            if (NHWC_OUT) {
                out[((size_t)b * Npix + n) * Cout + mlo]     = v0;
                out[((size_t)b * Npix + n) * Cout + mlo + 1] = v1;
            } else {
                out[((size_t)b * Cout + mlo) * Npix + n]       = v0;
                out[((size_t)b * Cout + mlo + 1) * Npix + n]   = v1;
            }
        }
    }
}

// --------- 8x8 f32x2 convT s=2 k=4 p=1 (post, dec1): BM x BN templated -----
template <int Cin, int Cout, int Hin, int Win, bool RELU, int BM, int BN>
__global__ void __launch_bounds__(256, 2)
tconv_gemm2(const float* __restrict__ in, const float* __restrict__ wt,
            const float* __restrict__ bias, float* __restrict__ out)
{
    constexpr int KK   = Cin * 4;
    constexpr int Hout = Hin * 2;
    constexpr int Wout = Win * 2;
    constexpr int TM   = BM / 8;            // thread rows
    constexpr int TN   = BN / 8;            // thread cols (TM*TN == 256)
    constexpr int BSW  = BN + (BN >> 5) * 4;

    __shared__ float As[16][BM];
    __shared__ float Bs[16][BSW];

    const int t    = threadIdx.x;
    const int n0   = blockIdx.x * BN;
    const int mcls = blockIdx.y;
    const int m0   = (mcls >> 2) * BM;
    const int cls  = mcls & 3;
    const int ph   = cls >> 1;
    const int pw   = cls & 1;
    const int b    = blockIdx.z;
    const int tm   = t / TN;
    const int tn   = t % TN;

    const float* inb  = in + (size_t)b * Cin * Hin * Win;
    const float* wcls = wt + (size_t)cls * Cout * KK;

    u64 acc[4][8];
#pragma unroll
    for (int p = 0; p < 4; p++)
#pragma unroll
        for (int j = 0; j < 8; j++) acc[p][j] = 0ull;

    const int pnb = pn(tn * 8);

    for (int kb = 0; kb < KK; kb += 16) {
        // ---- stage A (BM x 16) ----
        float4 avr[2048 / 256 / 4];   // (BM*16/256)/4 float4 per thread
        constexpr int APT = BM * 16 / 256;          // floats per thread (8 or 4)
        const int a_m = t / (16 / APT);             // BM=128: t>>1 ; BM=64: t>>2
        const int a_k = (t % (16 / APT)) * APT;
#pragma unroll
        for (int q = 0; q < APT / 4; q++)
            avr[q] = *(const float4*)(wcls + (size_t)(m0 + a_m) * KK + kb + a_k + 4 * q);

        // ---- stage B (16 x BN) ----
        constexpr int BPT = BN * 16 / 256;          // 8 (BN=128) or 16 (BN=256)
        const int bn  = (BPT == 16) ? t : (t & (BN - 1));
        const int bk0 = (BPT == 16) ? 0 : (t >> 7) * 8;
        const int ng  = n0 + bn;
        const int oy  = ng / Win;
        const int ox  = ng - oy * Win;
        float bv[BPT];
#pragma unroll
        for (int i = 0; i < BPT; i++) {
            int kk = kb + bk0 + i;
            int ci = kk >> 2;
            int tt = kk & 3;
            int ty = tt >> 1;
            int tx = tt & 1;
            int hi = oy + ph - ty;
            int wi = ox + pw - tx;
            float v = 0.f;
            if (hi >= 0 && hi < Hin && wi >= 0 && wi < Win)
                v = inb[(ci * Hin + hi) * Win + wi];
            bv[i] = v;
        }
        __syncthreads();
#pragma unroll
        for (int q = 0; q < APT / 4; q++) {
            As[a_k + 4 * q + 0][a_m] = avr[q].x;
            As[a_k + 4 * q + 1][a_m] = avr[q].y;
            As[a_k + 4 * q + 2][a_m] = avr[q].z;
            As[a_k + 4 * q + 3][a_m] = avr[q].w;
        }
        {
            int pb = pn(bn);
#pragma unroll
            for (int i = 0; i < BPT; i++) Bs[bk0 + i][pb] = bv[i];
        }
        __syncthreads();

#pragma unroll
        for (int k = 0; k < 16; k++) {
            ulonglong2 ax = *(const ulonglong2*)&As[k][tm * 8];
            ulonglong2 ay = *(const ulonglong2*)&As[k][tm * 8 + 4];
            u64 A[4] = {ax.x, ax.y, ay.x, ay.y};
            float4 b0 = *(const float4*)&Bs[k][pnb];
            float4 b1 = *(const float4*)&Bs[k][pnb + 4];
            u64 bd[8] = {dup2(b0.x), dup2(b0.y), dup2(b0.z), dup2(b0.w),
                         dup2(b1.x), dup2(b1.y), dup2(b1.z), dup2(b1.w)};
#pragma unroll
            for (int p = 0; p < 4; p++)
#pragma unroll
                for (int j = 0; j < 8; j++) ffma2(acc[p][j], A[p], bd[j]);
        }
    }

#pragma unroll
    for (int p = 0; p < 4; p++) {
        int mlo = m0 + tm * 8 + 2 * p;
        float blo = bias[mlo], bhi = bias[mlo + 1];
#pragma unroll
        for (int j = 0; j < 8; j++) {
            float lo, hi;
            unpack2(acc[p][j], lo, hi);
            float v0 = lo + blo;
            float v1 = hi + bhi;
            if (RELU) { v0 = fmaxf(v0, 0.f); v1 = fmaxf(v1, 0.f); }
            int n  = n0 + tn * 8 + j;
            int yy = n / Win;
            int xx = n - yy * Win;
            int ho = 2 * yy + ph;
            int wo = 2 * xx + pw;
            out[(((size_t)b * Cout + mlo) * Hout + ho) * Wout + wo]     = v0;
            out[(((size_t)b * Cout + mlo + 1) * Hout + ho) * Wout + wo] = v1;
        }
    }
}

template <int Cin, int Cout>
__global__ void repack_tconv(const float* __restrict__ w, float* __restrict__ wt)
{
    int idx = blockIdx.x * 256 + threadIdx.x;
    if (idx >= Cin * Cout * 16) return;
    int tt  = idx & 3;
    int t2  = idx >> 2;
    int ci  = t2 % Cin;
    int t3  = t2 / Cin;
    int co  = t3 % Cout;
    int cls = t3 / Cout;
    int ph = cls >> 1, pw = cls & 1;
    int ty = tt >> 1,  tx = tt & 1;
    int kh = ph ? (ty ? 2 : 0) : (ty ? 3 : 1);
    int kw = pw ? (tx ? 2 : 0) : (tx ? 3 : 1);
    wt[idx] = w[((ci * Cout + co) * 4 + kh) * 4 + kw];
}

__global__ void __launch_bounds__(256)
dec2_kernel(const float* __restrict__ in, const float* __restrict__ w,
            const float* __restrict__ bias, float* __restrict__ out)
{
    __shared__ float ws[3 * 64 * 9];
    for (int i = threadIdx.x; i < 3 * 64 * 9; i += 256) {
        int q  = i % 9;
        int ci = (i / 9) % 64;
        int co = i / (9 * 64);
        int kh = q / 3, kw = q % 3;
        ws[i] = w[((ci * 3 + co) * 3 + (2 - kh)) * 3 + (2 - kw)];
    }
    __syncthreads();

    int pix = blockIdx.x * 256 + threadIdx.x;
    int b  = pix >> 16;
    int p  = pix & 65535;
    int ho = p >> 8;
    int wo = p & 255;
    float a0 = bias[0], a1 = bias[1], a2 = bias[2];
    const float* inb = in + (size_t)b * 64 * 65536;
    for (int ci = 0; ci < 64; ci++) {
        float r[9];
#pragma unroll
        for (int kh = 0; kh < 3; kh++)
#pragma unroll
            for (int kw = 0; kw < 3; kw++) {
                int hi = ho - 1 + kh, wi = wo - 1 + kw;
                r[kh * 3 + kw] = (hi >= 0 && hi < 256 && wi >= 0 && wi < 256)
                                     ? inb[ci * 65536 + hi * 256 + wi] : 0.f;
            }
#pragma unroll
        for (int q = 0; q < 9; q++) {
            a0 += r[q] * ws[0 * 576 + ci * 9 + q];
            a1 += r[q] * ws[1 * 576 + ci * 9 + q];
            a2 += r[q] * ws[2 * 576 + ci * 9 + q];
        }
    }
    out[(b * 3 + 0) * 65536 + p] = a0;
    out[(b * 3 + 1) * 65536 + p] = a1;
    out[(b * 3 + 2) * 65536 + p] = a2;
}

// ------------------------------- VQ (FROZEN) -------------------------------
__global__ void zero_counts_kernel() { g_counts[threadIdx.x] = 0; }

__global__ void esq_kernel(const float* __restrict__ emb)
{
    int k = blockIdx.x * 128 + threadIdx.x;
    if (k < 512) {
        const float4* e = (const float4*)(emb + (size_t)k * 256);
        float s = 0.f;
#pragma unroll
        for (int i = 0; i < 64; i++) {
            float4 v = e[i];
            s += v.x * v.x + v.y * v.y + v.z * v.z + v.w * v.w;
        }
        g_esq[k] = s;
    }
}

__global__ void __launch_bounds__(256)
vq_kernel(const float* __restrict__ ze, const float* __restrict__ emb,
          float* __restrict__ zq_nhwc, float* __restrict__ zq_nchw)
{
    __shared__ float Zs[256][32];
    __shared__ float Es[32][64];
    __shared__ float zpart[32][8];
    __shared__ float zsqs[32];
    __shared__ float rbest[32][16];
    __shared__ int   rk[32][16];
    __shared__ int   fidx[32];

    const int t  = threadIdx.x;
    const int n0 = blockIdx.x * 32;
    const int tm = t >> 4;
    const int tn = t & 15;
    const int r0 = tm * 2, r1 = tm * 2 + 1;

#pragma unroll
    for (int j = 0; j < 8; j++) {
        int idx = t + 256 * j;
        int m   = idx >> 6;
        int kq  = idx & 63;
        float4 v = *(const float4*)(ze + ((size_t)(n0 + m)) * 256 + kq * 4);
        Zs[kq * 4 + 0][m] = v.x; Zs[kq * 4 + 1][m] = v.y;
        Zs[kq * 4 + 2][m] = v.z; Zs[kq * 4 + 3][m] = v.w;
    }
    __syncthreads();

    {
        int row = t & 31;
        int seg = t >> 5;
        float s = 0.f;
#pragma unroll
        for (int i = 0; i < 32; i++) {
            float v = Zs[seg * 32 + i][row];
            s += v * v;
        }
        zpart[row][seg] = s;
    }
    __syncthreads();
    if (t < 32) {
        float s = zpart[t][0];
#pragma unroll
        for (int q = 1; q < 8; q++) s += zpart[t][q];
        zsqs[t] = s;
    }
    __syncthreads();

    const float zr0 = zsqs[r0];
    const float zr1 = zsqs[r1];

    float best[2] = {1e30f, 1e30f};
    int   bk[2]   = {0, 0};

    for (int e0 = 0; e0 < 512; e0 += 64) {
        float acc[8][2][2];
        float acc2[8][2][2];
#pragma unroll
        for (int l = 0; l < 8; l++)
#pragma unroll
            for (int i = 0; i < 2; i++)
#pragma unroll
                for (int j = 0; j < 2; j++) { acc[l][i][j] = 0.f; acc2[l][i][j] = 0.f; }

        for (int kb = 0; kb < 256; kb += 32) {
            __syncthreads();
#pragma unroll
            for (int j = 0; j < 2; j++) {
                int idx = t + 256 * j;
                int e   = idx >> 3;
                int k4  = (idx & 7) * 4;
                float4 v = *(const float4*)(emb + (size_t)(e0 + e) * 256 + kb + k4);
                Es[k4 + 0][e] = v.x; Es[k4 + 1][e] = v.y;
                Es[k4 + 2][e] = v.z; Es[k4 + 3][e] = v.w;
            }
            __syncthreads();
#pragma unroll
            for (int k = 0; k < 32; k++) {
                const int l = k & 7;
                float a0 = Zs[kb + k][r0];
                float a1 = Zs[kb + k][r1];
                float4 bq = *(const float4*)&Es[k][tn * 4];
                acc [l][0][0] = __fmaf_rn(a0, bq.x, acc [l][0][0]);
                acc [l][0][1] = __fmaf_rn(a0, bq.y, acc [l][0][1]);
                acc2[l][0][0] = __fmaf_rn(a0, bq.z, acc2[l][0][0]);
                acc2[l][0][1] = __fmaf_rn(a0, bq.w, acc2[l][0][1]);
                acc [l][1][0] = __fmaf_rn(a1, bq.x, acc [l][1][0]);
                acc [l][1][1] = __fmaf_rn(a1, bq.y, acc [l][1][1]);
                acc2[l][1][0] = __fmaf_rn(a1, bq.z, acc2[l][1][0]);
                acc2[l][1][1] = __fmaf_rn(a1, bq.w, acc2[l][1][1]);
            }
        }
#pragma unroll
        for (int i = 0; i < 2; i++) {
            float zr = (i == 0) ? zr0 : zr1;
#pragma unroll
            for (int j = 0; j < 4; j++) {
                float d;
                if (j < 2) {
                    float q0 = __fadd_rn(acc[0][i][j], acc[4][i][j]);
                    float q1 = __fadd_rn(acc[1][i][j], acc[5][i][j]);
                    float q2 = __fadd_rn(acc[2][i][j], acc[6][i][j]);
                    float q3 = __fadd_rn(acc[3][i][j], acc[7][i][j]);
                    d = __fadd_rn(__fadd_rn(q0, q2), __fadd_rn(q1, q3));
                } else {
                    int jj = j - 2;
                    float q0 = __fadd_rn(acc2[0][i][jj], acc2[4][i][jj]);
                    float q1 = __fadd_rn(acc2[1][i][jj], acc2[5][i][jj]);
                    float q2 = __fadd_rn(acc2[2][i][jj], acc2[6][i][jj]);
                    float q3 = __fadd_rn(acc2[3][i][jj], acc2[7][i][jj]);
                    d = __fadd_rn(__fadd_rn(q0, q2), __fadd_rn(q1, q3));
                }
                int kcode = e0 + tn * 4 + j;
                float eq = g_esq[kcode];
                float s = __fadd_rn(__fadd_rn(zr, eq), -__fmul_rn(2.f, d));
                if (s < best[i]) { best[i] = s; bk[i] = kcode; }
            }
        }
    }
    __syncthreads();
    rbest[r0][tn] = best[0]; rk[r0][tn] = bk[0];
    rbest[r1][tn] = best[1]; rk[r1][tn] = bk[1];
    __syncthreads();
    if (t < 32) {
        float bs = rbest[t][0];
        int   bi = rk[t][0];
#pragma unroll
        for (int q = 1; q < 16; q++) {
            float s = rbest[t][q];
            int   k = rk[t][q];
            if (s < bs || (s == bs && k < bi)) { bs = s; bi = k; }
        }
        fidx[t] = bi;
        atomicAdd(&g_counts[bi], 1);
    }
    __syncthreads();

#pragma unroll
    for (int j = 0; j < 8; j++) {
        int idx = t + 256 * j;
        int m   = idx >> 6;
        int d4  = idx & 63;
        float4 v = *(const float4*)(emb + (size_t)fidx[m] * 256 + d4 * 4);
        *(float4*)(zq_nhwc + ((size_t)(n0 + m)) * 256 + d4 * 4) = v;
    }
    {
        int lane = t & 31, wrp = t >> 5;
        int n    = n0 + lane;
        int bimg = n >> 12;
        int pixl = n & 4095;
        int code = fidx[lane];
#pragma unroll
        for (int j = 0; j < 32; j++) {
            int d = wrp + 8 * j;
            float qv  = emb[(size_t)code * 256 + d];
            float zev = Zs[d][lane];
            zq_nchw[(((size_t)bimg * 256 + d) << 12) + pixl] = zev + (qv - zev);
        }
    }
}

__global__ void perp_kernel(float* __restrict__ out)
{
    __shared__ float red[512];
    int t = threadIdx.x;
    float p = (float)g_counts[t] * (1.f / 65536.f);
    red[t] = p * logf(p + 1e-10f);
    __syncthreads();
    for (int s = 256; s > 0; s >>= 1) {
        if (t < s) red[t] += red[t + s];
        __syncthreads();
    }
    if (t == 0) out[0] = expf(-red[0]);
}

// ---------------------------------------------------------------------------
extern "C" void kernel_launch(void* const* d_in, const int* in_sizes, int n_in,
                              void* d_out, int out_size)
{
    const float* x      = (const float*)d_in[0];
    const float* w_enc1 = (const float*)d_in[1];
    const float* b_enc1 = (const float*)d_in[2];
    const float* w_enc2 = (const float*)d_in[3];
    const float* b_enc2 = (const float*)d_in[4];
    const float* w_prevq= (const float*)d_in[5];
    const float* b_prevq= (const float*)d_in[6];
    const float* emb    = (const float*)d_in[7];
    const float* w_post = (const float*)d_in[8];
    const float* b_post = (const float*)d_in[9];
    const float* w_dec1 = (const float*)d_in[10];
    const float* b_dec1 = (const float*)d_in[11];
    const float* w_dec2 = (const float*)d_in[12];
    const float* b_dec2 = (const float*)d_in[13];

    float* out  = (float*)d_out;
    float* ze   = out + OFF_ZE;
    float* zq   = out + OFF_ZQ;
    float* perp = out + OFF_PERP;

    void* p;
    cudaGetSymbolAddress(&p, g_h1);       float* h1  = (float*)p;
    cudaGetSymbolAddress(&p, g_h2);       float* h2  = (float*)p;
    cudaGetSymbolAddress(&p, g_zq_nchw);  float* zqn = (float*)p;
    cudaGetSymbolAddress(&p, g_d1);       float* d1  = (float*)p;
    cudaGetSymbolAddress(&p, g_d2);       float* d2  = (float*)p;
    cudaGetSymbolAddress(&p, g_wt_post);  float* wtp = (float*)p;
    cudaGetSymbolAddress(&p, g_wt_dec1);  float* wtd = (float*)p;
    cudaGetSymbolAddress(&p, g_wc1);      float* wc1 = (float*)p;
    cudaGetSymbolAddress(&p, g_wc2);      float* wc2 = (float*)p;
    cudaGetSymbolAddress(&p, g_wc3);      float* wc3 = (float*)p;

    zero_counts_kernel<<<1, 512>>>();
    esq_kernel<<<4, 128>>>(emb);
    repack_conv<3, 64, 4><<<12, 256>>>(w_enc1, wc1);
    repack_conv<64, 128, 4><<<512, 256>>>(w_enc2, wc2);
    repack_conv<128, 256, 3><<<1152, 256>>>(w_prevq, wc3);
    repack_tconv<256, 128><<<2048, 256>>>(w_post, wtp);
    repack_tconv<128, 64><<<512, 256>>>(w_dec1, wtd);

    // encoder (bit-frozen numerics; enc2/prevq use FFMA2 8x8 — bit-identical)
    conv_gemm<3, 64, 4, 2, 1, 256, 256, 128, 128, true, false>
        <<<dim3(256, 1, 16), 256>>>(x, wc1, b_enc1, h1);
    conv_gemm2<64, 128, 4, 2, 1, 128, 128, 64, 64, true, false>
        <<<dim3(32, 1, 16), 256>>>(h1, wc2, b_enc2, h2);
    conv_gemm2<128, 256, 3, 1, 1, 64, 64, 64, 64, false, true>
        <<<dim3(32, 2, 16), 256>>>(h2, wc3, b_prevq, ze);

    vq_kernel<<<2048, 256>>>(ze, emb, zq, zqn);
    perp_kernel<<<1, 512>>>(perp);

    // decoder
    tconv_gemm2<256, 128, 64, 64, false, 128, 128>
        <<<dim3(32, 4, 16), 256>>>(zqn, wtp, b_post, d1);
    tconv_gemm2<128, 64, 128, 128, true, 64, 256>
        <<<dim3(64, 4, 16), 256>>>(d1, wtd, b_dec1, d2);
    dec2_kernel<<<4096, 256>>>(d2, w_dec2, b_dec2, out);
}

// round 13
// speedup vs baseline: 1.2400x; 1.0298x over previous
#include <cuda_runtime.h>
#include <math.h>

// ---------------------------------------------------------------------------
// VQ-VAE forward, fp32. FROZEN NUMERICS (pass @ rel_err 2.58e-6):
//  - enc convs: kw-major ci-fastest k-order, single ascending FMA chain
//  - VQ dot: 8 interleaved accumulators + shuffle-halving combine
//  - score s = fl(fl(zsq+esq) - fl(2*dot)), ties -> lowest index
// Perf: FFMA2 (fma.rn.f32x2, lane-wise IEEE rn) 8x8 tiles + double-buffered
// smem staging for enc2/prevq/post/dec1; FFMA2 code-pair VQ.
// ---------------------------------------------------------------------------

#define OFF_ZE   3145728
#define OFF_ZQ   19922944
#define OFF_PERP 36700160

typedef unsigned long long u64;

__device__ __forceinline__ void ffma2(u64& acc, u64 a, u64 b)
{
    asm("fma.rn.f32x2 %0, %1, %2, %0;" : "+l"(acc) : "l"(a), "l"(b));
}
__device__ __forceinline__ u64 dup2(float x)
{
    u64 r;
    asm("mov.b64 %0, {%1, %1};" : "=l"(r) : "r"(__float_as_uint(x)));
    return r;
}
__device__ __forceinline__ void unpack2(u64 v, float& lo, float& hi)
{
    unsigned a, b;
    asm("mov.b64 {%0, %1}, %2;" : "=r"(a), "=r"(b) : "l"(v));
    lo = __uint_as_float(a); hi = __uint_as_float(b);
}
__device__ __forceinline__ int pn(int n) { return n + ((n >> 5) << 2); }

// ------------------------- scratch (device globals) -----------------------
__device__ float g_h1[16 * 64 * 128 * 128];
__device__ float g_h2[16 * 128 * 64 * 64];
__device__ float g_zq_nchw[16 * 256 * 64 * 64];
__device__ float g_d1[16 * 128 * 128 * 128];
__device__ float g_d2[16 * 64 * 256 * 256];
__device__ float g_wt_post[4 * 128 * 256 * 4];
__device__ float g_wt_dec1[4 * 64 * 128 * 4];
__device__ float g_wc1[64 * 48];
__device__ float g_wc2[128 * 1024];
__device__ float g_wc3[256 * 1152];
__device__ float g_esq[512];
__device__ int   g_counts[512];

template <int Cin, int Cout, int KS>
__global__ void repack_conv(const float* __restrict__ w, float* __restrict__ wr)
{
    int idx = blockIdx.x * 256 + threadIdx.x;
    if (idx >= Cout * Cin * KS * KS) return;
    int ci = idx % Cin;
    int t  = idx / Cin;
    int kh = t % KS;
    int t2 = t / KS;
    int kw = t2 % KS;
    int co = t2 / KS;
    wr[idx] = w[((co * Cin + ci) * KS + kh) * KS + kw];
}

// --------------------- 4x4 conv (enc1 only; frozen) ------------------------
template <int Cin, int Cout, int KS, int S, int P,
          int Hin, int Win, int Hout, int Wout, bool RELU, bool NHWC_OUT>
__global__ void __launch_bounds__(256)
conv_gemm(const float* __restrict__ in, const float* __restrict__ w,
          const float* __restrict__ bias, float* __restrict__ out)
{
    constexpr int KK   = Cin * KS * KS;
    constexpr int Npix = Hout * Wout;

    __shared__ float As[16][64];
    __shared__ float Bs[16][64];

    const int t  = threadIdx.x;
    const int n0 = blockIdx.x * 64;
    const int m0 = blockIdx.y * 64;
    const int b  = blockIdx.z;
    const int tm = t >> 4;
    const int tn = t & 15;
    const int ma = t >> 2;
    const int ka = (t & 3) << 2;
    const int nb  = t & 63;
    const int kb0 = t >> 6;

    const int nglob = n0 + nb;
    const int ho_b  = nglob / Wout;
    const int wo_b  = nglob - ho_b * Wout;
    const float* inb = in + (size_t)b * Cin * Hin * Win;

    float acc[4][4];
#pragma unroll
    for (int i = 0; i < 4; i++)
#pragma unroll
        for (int j = 0; j < 4; j++) acc[i][j] = 0.f;

    for (int kb = 0; kb < KK; kb += 16) {
        float4 av = *(const float4*)(w + (size_t)(m0 + ma) * KK + kb + ka);
        float bv[4];
#pragma unroll
        for (int j = 0; j < 4; j++) {
            int kk = kb + kb0 + 4 * j;
            int ci = kk % Cin;
            int r  = kk / Cin;
            int kh = r % KS;
            int kw = r / KS;
            int hi = ho_b * S - P + kh;
            int wi = wo_b * S - P + kw;
            float v = 0.f;
            if (hi >= 0 && hi < Hin && wi >= 0 && wi < Win)
                v = inb[(ci * Hin + hi) * Win + wi];
            bv[j] = v;
        }
        __syncthreads();
        As[ka + 0][ma] = av.x; As[ka + 1][ma] = av.y;
        As[ka + 2][ma] = av.z; As[ka + 3][ma] = av.w;
#pragma unroll
        for (int j = 0; j < 4; j++) Bs[kb0 + 4 * j][nb] = bv[j];
        __syncthreads();

#pragma unroll
        for (int k = 0; k < 16; k++) {
            float4 a  = *(const float4*)&As[k][tm * 4];
            float4 bq = *(const float4*)&Bs[k][tn * 4];
            float ar[4] = {a.x, a.y, a.z, a.w};
            float br[4] = {bq.x, bq.y, bq.z, bq.w};
#pragma unroll
            for (int i = 0; i < 4; i++)
#pragma unroll
                for (int j = 0; j < 4; j++) acc[i][j] += ar[i] * br[j];
        }
    }

#pragma unroll
    for (int i = 0; i < 4; i++) {
        int m = m0 + tm * 4 + i;
        float bb = bias[m];
#pragma unroll
        for (int j = 0; j < 4; j++) {
            float v = acc[i][j] + bb;
            if (RELU) v = fmaxf(v, 0.f);
            int n = n0 + tn * 4 + j;
            if (NHWC_OUT)
                out[((size_t)b * Npix + n) * Cout + m] = v;
            else
                out[((size_t)b * Cout + m) * Npix + n] = v;
        }
    }
}

// ------- 8x8 f32x2 conv, double-buffered (enc2, prevq): BM=BN=128 ----------
template <int Cin, int Cout, int KS, int S, int P,
          int Hin, int Win, int Hout, int Wout, bool RELU, bool NHWC_OUT>
__global__ void __launch_bounds__(256, 2)
conv_gemm2(const float* __restrict__ in, const float* __restrict__ w,
           const float* __restrict__ bias, float* __restrict__ out)
{
    constexpr int KK   = Cin * KS * KS;
    constexpr int Npix = Hout * Wout;
    constexpr int NT   = KK / 16;

    __shared__ float As[2][16][128];
    __shared__ float Bs[2][16][144];

    const int t  = threadIdx.x;
    const int n0 = blockIdx.x * 128;
    const int m0 = blockIdx.y * 128;
    const int b  = blockIdx.z;
    const int tm = t >> 4;
    const int tn = t & 15;

    const int a_m = t >> 1;
    const int a_k = (t & 1) * 8;
    const int bn  = t & 127;
    const int kk0 = (t >> 7) * 8;
    const int pb  = pn(bn);

    const int nglob = n0 + bn;
    const int ho_b  = nglob / Wout;
    const int wo_b  = nglob - ho_b * Wout;
    const float* inb = in + (size_t)b * Cin * Hin * Win;
    const float* wrow = w + (size_t)(m0 + a_m) * KK + a_k;

    u64 acc[4][8];
#pragma unroll
    for (int p = 0; p < 4; p++)
#pragma unroll
        for (int j = 0; j < 8; j++) acc[p][j] = 0ull;

    const int pnb = pn(tn * 8);

    float4 av0, av1;
    float  bv[8];

#define LOAD_TILE(KB)                                                        \
    {                                                                        \
        av0 = *(const float4*)(wrow + (KB));                                 \
        av1 = *(const float4*)(wrow + (KB) + 4);                             \
        _Pragma("unroll")                                                    \
        for (int i = 0; i < 8; i++) {                                        \
            int kk = (KB) + kk0 + i;                                         \
            int ci = kk % Cin;                                               \
            int r  = kk / Cin;                                               \
            int kh = r % KS;                                                 \
            int kw = r / KS;                                                 \
            int hi = ho_b * S - P + kh;                                      \
            int wi = wo_b * S - P + kw;                                      \
            float v = 0.f;                                                   \
            if (hi >= 0 && hi < Hin && wi >= 0 && wi < Win)                  \
                v = inb[(ci * Hin + hi) * Win + wi];                         \
            bv[i] = v;                                                       \
        }                                                                    \
    }
#define STORE_TILE(BUF)                                                      \
    {                                                                        \
        As[BUF][a_k + 0][a_m] = av0.x; As[BUF][a_k + 1][a_m] = av0.y;        \
        As[BUF][a_k + 2][a_m] = av0.z; As[BUF][a_k + 3][a_m] = av0.w;        \
        As[BUF][a_k + 4][a_m] = av1.x; As[BUF][a_k + 5][a_m] = av1.y;        \
        As[BUF][a_k + 6][a_m] = av1.z; As[BUF][a_k + 7][a_m] = av1.w;        \
        _Pragma("unroll")                                                    \
        for (int i = 0; i < 8; i++) Bs[BUF][kk0 + i][pb] = bv[i];            \
    }

    LOAD_TILE(0);
    STORE_TILE(0);
    __syncthreads();

    for (int it = 0; it < NT; it++) {
        const int cur = it & 1;
        if (it + 1 < NT) LOAD_TILE((it + 1) * 16);

#pragma unroll
        for (int k = 0; k < 16; k++) {
            ulonglong2 ax = *(const ulonglong2*)&As[cur][k][tm * 8];
            ulonglong2 ay = *(const ulonglong2*)&As[cur][k][tm * 8 + 4];
            u64 A[4] = {ax.x, ax.y, ay.x, ay.y};
            float4 b0 = *(const float4*)&Bs[cur][k][pnb];
            float4 b1 = *(const float4*)&Bs[cur][k][pnb + 4];
            u64 bd[8] = {dup2(b0.x), dup2(b0.y), dup2(b0.z), dup2(b0.w),
                         dup2(b1.x), dup2(b1.y), dup2(b1.z), dup2(b1.w)};
#pragma unroll
            for (int p = 0; p < 4; p++)
#pragma unroll
                for (int j = 0; j < 8; j++) ffma2(acc[p][j], A[p], bd[j]);
        }
        if (it + 1 < NT) STORE_TILE(cur ^ 1);
        __syncthreads();
    }
#undef LOAD_TILE
#undef STORE_TILE

#pragma unroll
    for (int p = 0; p < 4; p++) {
        int mlo = m0 + tm * 8 + 2 * p;
        float blo = bias[mlo], bhi = bias[mlo + 1];
#pragma unroll
        for (int j = 0; j < 8; j++) {
            float lo, hi;
            unpack2(acc[p][j], lo, hi);
            float v0 = lo + blo;
            float v1 = hi + bhi;
            if (RELU) { v0 = fmaxf(v0, 0.f); v1 = fmaxf(v1, 0.f); }
            int n = n0 + tn * 8 + j;
            if (NHWC_OUT) {
                out[((size_t)b * Npix + n) * Cout + mlo]     = v0;
                out[((size_t)b * Npix + n) * Cout + mlo + 1] = v1;
            } else {
                out[((size_t)b * Cout + mlo) * Npix + n]       = v0;
                out[((size_t)b * Cout + mlo + 1) * Npix + n]   = v1;
            }
        }
    }
}

// ---- 8x8 f32x2 convT, double-buffered (post, dec1): BM x BN templated -----
template <int Cin, int Cout, int Hin, int Win, bool RELU, int BM, int BN>
__global__ void __launch_bounds__(256, 2)
tconv_gemm2(const float* __restrict__ in, const float* __restrict__ wt,
            const float* __restrict__ bias, float* __restrict__ out)
{
    constexpr int KK   = Cin * 4;
    constexpr int Hout = Hin * 2;
    constexpr int Wout = Win * 2;
    constexpr int TN   = BN / 8;
    constexpr int BSW  = BN + (BN >> 5) * 4;
    constexpr int NT   = KK / 16;
    constexpr int APT  = BM * 16 / 256;
    constexpr int BPT  = BN * 16 / 256;

    __shared__ float As[2][16][BM];
    __shared__ float Bs[2][16][BSW];

    const int t    = threadIdx.x;
    const int n0   = blockIdx.x * BN;
    const int mcls = blockIdx.y;
    const int m0   = (mcls >> 2) * BM;
    const int cls  = mcls & 3;
    const int ph   = cls >> 1;
    const int pw   = cls & 1;
    const int b    = blockIdx.z;
    const int tm   = t / TN;
    const int tn   = t % TN;

    const float* inb  = in + (size_t)b * Cin * Hin * Win;
    const float* wcls = wt + (size_t)cls * Cout * KK;

    const int a_m = t / (16 / APT);
    const int a_k = (t % (16 / APT)) * APT;
    const int bn  = (BPT == 16) ? t : (t & (BN - 1));
    const int bk0 = (BPT == 16) ? 0 : (t >> 7) * 8;
    const int pb  = pn(bn);
    const int ng  = n0 + bn;
    const int oy  = ng / Win;
    const int ox  = ng - oy * Win;
    const float* warow = wcls + (size_t)(m0 + a_m) * KK + a_k;

    u64 acc[4][8];
#pragma unroll
    for (int p = 0; p < 4; p++)
#pragma unroll
        for (int j = 0; j < 8; j++) acc[p][j] = 0ull;

    const int pnb = pn(tn * 8);

    float4 avr[APT / 4];
    float  bv[BPT];

#define T_LOAD(KB)                                                           \
    {                                                                        \
        _Pragma("unroll")                                                    \
        for (int q = 0; q < APT / 4; q++)                                    \
            avr[q] = *(const float4*)(warow + (KB) + 4 * q);                 \
        _Pragma("unroll")                                                    \
        for (int i = 0; i < BPT; i++) {                                      \
            int kk = (KB) + bk0 + i;                                         \
            int ci = kk >> 2;                                                \
            int tt = kk & 3;                                                 \
            int ty = tt >> 1;                                                \
            int tx = tt & 1;                                                 \
            int hi = oy + ph - ty;                                           \
            int wi = ox + pw - tx;                                           \
            float v = 0.f;                                                   \
            if (hi >= 0 && hi < Hin && wi >= 0 && wi < Win)                  \
                v = inb[(ci * Hin + hi) * Win + wi];                         \
            bv[i] = v;                                                       \
        }                                                                    \
    }
#define T_STORE(BUF)                                                         \
    {                                                                        \
        _Pragma("unroll")                                                    \
        for (int q = 0; q < APT / 4; q++) {                                  \
            As[BUF][a_k + 4 * q + 0][a_m] = avr[q].x;                        \
            As[BUF][a_k + 4 * q + 1][a_m] = avr[q].y;                        \
            As[BUF][a_k + 4 * q + 2][a_m] = avr[q].z;                        \
            As[BUF][a_k + 4 * q + 3][a_m] = avr[q].w;                        \
        }                                                                    \
        _Pragma("unroll")                                                    \
        for (int i = 0; i < BPT; i++) Bs[BUF][bk0 + i][pb] = bv[i];          \
    }

    T_LOAD(0);
    T_STORE(0);
    __syncthreads();

    for (int it = 0; it < NT; it++) {
        const int cur = it & 1;
        if (it + 1 < NT) T_LOAD((it + 1) * 16);

#pragma unroll
        for (int k = 0; k < 16; k++) {
            ulonglong2 ax = *(const ulonglong2*)&As[cur][k][tm * 8];
            ulonglong2 ay = *(const ulonglong2*)&As[cur][k][tm * 8 + 4];
            u64 A[4] = {ax.x, ax.y, ay.x, ay.y};
            float4 b0 = *(const float4*)&Bs[cur][k][pnb];
            float4 b1 = *(const float4*)&Bs[cur][k][pnb + 4];
            u64 bd[8] = {dup2(b0.x), dup2(b0.y), dup2(b0.z), dup2(b0.w),
                         dup2(b1.x), dup2(b1.y), dup2(b1.z), dup2(b1.w)};
#pragma unroll
            for (int p = 0; p < 4; p++)
#pragma unroll
                for (int j = 0; j < 8; j++) ffma2(acc[p][j], A[p], bd[j]);
        }
        if (it + 1 < NT) T_STORE(cur ^ 1);
        __syncthreads();
    }
#undef T_LOAD
#undef T_STORE

#pragma unroll
    for (int p = 0; p < 4; p++) {
        int mlo = m0 + tm * 8 + 2 * p;
        float blo = bias[mlo], bhi = bias[mlo + 1];
#pragma unroll
        for (int j = 0; j < 8; j++) {
            float lo, hi;
            unpack2(acc[p][j], lo, hi);
            float v0 = lo + blo;
            float v1 = hi + bhi;
            if (RELU) { v0 = fmaxf(v0, 0.f); v1 = fmaxf(v1, 0.f); }
            int n  = n0 + tn * 8 + j;
            int yy = n / Win;
            int xx = n - yy * Win;
            int ho = 2 * yy + ph;
            int wo = 2 * xx + pw;
            out[(((size_t)b * Cout + mlo) * Hout + ho) * Wout + wo]     = v0;
            out[(((size_t)b * Cout + mlo + 1) * Hout + ho) * Wout + wo] = v1;
        }
    }
}

template <int Cin, int Cout>
__global__ void repack_tconv(const float* __restrict__ w, float* __restrict__ wt)
{
    int idx = blockIdx.x * 256 + threadIdx.x;
    if (idx >= Cin * Cout * 16) return;
    int tt  = idx & 3;
    int t2  = idx >> 2;
    int ci  = t2 % Cin;
    int t3  = t2 / Cin;
    int co  = t3 % Cout;
    int cls = t3 / Cout;
    int ph = cls >> 1, pw = cls & 1;
    int ty = tt >> 1,  tx = tt & 1;
    int kh = ph ? (ty ? 2 : 0) : (ty ? 3 : 1);
    int kw = pw ? (tx ? 2 : 0) : (tx ? 3 : 1);
    wt[idx] = w[((ci * Cout + co) * 4 + kh) * 4 + kw];
}

__global__ void __launch_bounds__(256)
dec2_kernel(const float* __restrict__ in, const float* __restrict__ w,
            const float* __restrict__ bias, float* __restrict__ out)
{
    __shared__ float ws[3 * 64 * 9];
    for (int i = threadIdx.x; i < 3 * 64 * 9; i += 256) {
        int q  = i % 9;
        int ci = (i / 9) % 64;
        int co = i / (9 * 64);
        int kh = q / 3, kw = q % 3;
        ws[i] = w[((ci * 3 + co) * 3 + (2 - kh)) * 3 + (2 - kw)];
    }
    __syncthreads();

    int pix = blockIdx.x * 256 + threadIdx.x;
    int b  = pix >> 16;
    int p  = pix & 65535;
    int ho = p >> 8;
    int wo = p & 255;
    float a0 = bias[0], a1 = bias[1], a2 = bias[2];
    const float* inb = in + (size_t)b * 64 * 65536;
    for (int ci = 0; ci < 64; ci++) {
        float r[9];
#pragma unroll
        for (int kh = 0; kh < 3; kh++)
#pragma unroll
            for (int kw = 0; kw < 3; kw++) {
                int hi = ho - 1 + kh, wi = wo - 1 + kw;
                r[kh * 3 + kw] = (hi >= 0 && hi < 256 && wi >= 0 && wi < 256)
                                     ? inb[ci * 65536 + hi * 256 + wi] : 0.f;
            }
#pragma unroll
        for (int q = 0; q < 9; q++) {
            a0 += r[q] * ws[0 * 576 + ci * 9 + q];
            a1 += r[q] * ws[1 * 576 + ci * 9 + q];
            a2 += r[q] * ws[2 * 576 + ci * 9 + q];
        }
    }
    out[(b * 3 + 0) * 65536 + p] = a0;
    out[(b * 3 + 1) * 65536 + p] = a1;
    out[(b * 3 + 2) * 65536 + p] = a2;
}

// ------------------------------- VQ (bit-frozen chains, FFMA2 code-pairs) --
__global__ void zero_counts_kernel() { g_counts[threadIdx.x] = 0; }

__global__ void esq_kernel(const float* __restrict__ emb)
{
    int k = blockIdx.x * 128 + threadIdx.x;
    if (k < 512) {
        const float4* e = (const float4*)(emb + (size_t)k * 256);
        float s = 0.f;
#pragma unroll
        for (int i = 0; i < 64; i++) {
            float4 v = e[i];
            s += v.x * v.x + v.y * v.y + v.z * v.z + v.w * v.w;
        }
        g_esq[k] = s;
    }
}

__global__ void __launch_bounds__(256)
vq_kernel(const float* __restrict__ ze, const float* __restrict__ emb,
          float* __restrict__ zq_nhwc, float* __restrict__ zq_nchw)
{
    __shared__ u64   Zsd[256][32];   // {z,z} per (d,row) — 64KB
    __shared__ float Es[32][64];
    __shared__ float zpart[32][8];
    __shared__ float zsqs[32];
    __shared__ float rbest[32][16];
    __shared__ int   rk[32][16];
    __shared__ int   fidx[32];

    const int t  = threadIdx.x;
    const int n0 = blockIdx.x * 32;
    const int tm = t >> 4;
    const int tn = t & 15;
    const int r0 = tm * 2, r1 = tm * 2 + 1;

#pragma unroll
    for (int j = 0; j < 8; j++) {
        int idx = t + 256 * j;
        int m   = idx >> 6;
        int kq  = idx & 63;
        float4 v = *(const float4*)(ze + ((size_t)(n0 + m)) * 256 + kq * 4);
        Zsd[kq * 4 + 0][m] = dup2(v.x); Zsd[kq * 4 + 1][m] = dup2(v.y);
        Zsd[kq * 4 + 2][m] = dup2(v.z); Zsd[kq * 4 + 3][m] = dup2(v.w);
    }
    __syncthreads();

    {   // per-row |z|^2 fp32 (argmin-irrelevant; same value order as before)
        int row = t & 31;
        int seg = t >> 5;
        float s = 0.f;
#pragma unroll
        for (int i = 0; i < 32; i++) {
            float v = ((const float*)&Zsd[seg * 32 + i][row])[0];
            s += v * v;
        }
        zpart[row][seg] = s;
    }
    __syncthreads();
    if (t < 32) {
        float s = zpart[t][0];
#pragma unroll
        for (int q = 1; q < 8; q++) s += zpart[t][q];
        zsqs[t] = s;
    }
    __syncthreads();

    const float zr0 = zsqs[r0];
    const float zr1 = zsqs[r1];

    float best[2] = {1e30f, 1e30f};
    int   bk[2]   = {0, 0};

    for (int e0 = 0; e0 < 512; e0 += 64) {
        // accP[l][row][codepair]: lanes = (code tn*4+2cp, +1); chains per
        // (row, code, l) identical to the frozen scalar version.
        u64 accP[8][2][2];
#pragma unroll
        for (int l = 0; l < 8; l++)
#pragma unroll
            for (int i = 0; i < 2; i++)
#pragma unroll
                for (int cp = 0; cp < 2; cp++) accP[l][i][cp] = 0ull;

        for (int kb = 0; kb < 256; kb += 32) {
            __syncthreads();
#pragma unroll
            for (int j = 0; j < 2; j++) {
                int idx = t + 256 * j;
                int e   = idx >> 3;
                int k4  = (idx & 7) * 4;
                float4 v = *(const float4*)(emb + (size_t)(e0 + e) * 256 + kb + k4);
                Es[k4 + 0][e] = v.x; Es[k4 + 1][e] = v.y;
                Es[k4 + 2][e] = v.z; Es[k4 + 3][e] = v.w;
            }
            __syncthreads();
#pragma unroll
            for (int k = 0; k < 32; k++) {
                const int l = k & 7;
                u64 A0 = Zsd[kb + k][r0];            // {a0,a0}
                u64 A1 = Zsd[kb + k][r1];            // {a1,a1}
                ulonglong2 B = *(const ulonglong2*)&Es[k][tn * 4]; // code pairs
                ffma2(accP[l][0][0], A0, B.x);
                ffma2(accP[l][0][1], A0, B.y);
                ffma2(accP[l][1][0], A1, B.x);
                ffma2(accP[l][1][1], A1, B.y);
            }
        }
#pragma unroll
        for (int i = 0; i < 2; i++) {
            float zr = (i == 0) ? zr0 : zr1;
#pragma unroll
            for (int cp = 0; cp < 2; cp++) {
                float v0[8], v1[8];
#pragma unroll
                for (int l = 0; l < 8; l++) unpack2(accP[l][i][cp], v0[l], v1[l]);
                // code 2*cp (lo lanes)
                {
                    float q0 = __fadd_rn(v0[0], v0[4]);
                    float q1 = __fadd_rn(v0[1], v0[5]);
                    float q2 = __fadd_rn(v0[2], v0[6]);
                    float q3 = __fadd_rn(v0[3], v0[7]);
                    float d  = __fadd_rn(__fadd_rn(q0, q2), __fadd_rn(q1, q3));
                    int kcode = e0 + tn * 4 + 2 * cp;
                    float eq = g_esq[kcode];
                    float s = __fadd_rn(__fadd_rn(zr, eq), -__fmul_rn(2.f, d));
                    if (s < best[i]) { best[i] = s; bk[i] = kcode; }
                }
                // code 2*cp+1 (hi lanes)
                {
                    float q0 = __fadd_rn(v1[0], v1[4]);
                    float q1 = __fadd_rn(v1[1], v1[5]);
                    float q2 = __fadd_rn(v1[2], v1[6]);
                    float q3 = __fadd_rn(v1[3], v1[7]);
                    float d  = __fadd_rn(__fadd_rn(q0, q2), __fadd_rn(q1, q3));
                    int kcode = e0 + tn * 4 + 2 * cp + 1;
                    float eq = g_esq[kcode];
                    float s = __fadd_rn(__fadd_rn(zr, eq), -__fmul_rn(2.f, d));
                    if (s < best[i]) { best[i] = s; bk[i] = kcode; }
                }
            }
        }
    }
    __syncthreads();
    rbest[r0][tn] = best[0]; rk[r0][tn] = bk[0];
    rbest[r1][tn] = best[1]; rk[r1][tn] = bk[1];
    __syncthreads();
    if (t < 32) {
        float bs = rbest[t][0];
        int   bi = rk[t][0];
#pragma unroll
        for (int q = 1; q < 16; q++) {
            float s = rbest[t][q];
            int   k = rk[t][q];
            if (s < bs || (s == bs && k < bi)) { bs = s; bi = k; }
        }
        fidx[t] = bi;
        atomicAdd(&g_counts[bi], 1);
    }
    __syncthreads();

#pragma unroll
    for (int j = 0; j < 8; j++) {
        int idx = t + 256 * j;
        int m   = idx >> 6;
        int d4  = idx & 63;
        float4 v = *(const float4*)(emb + (size_t)fidx[m] * 256 + d4 * 4);
        *(float4*)(zq_nhwc + ((size_t)(n0 + m)) * 256 + d4 * 4) = v;
    }
    {
        int lane = t & 31, wrp = t >> 5;
        int n    = n0 + lane;
        int bimg = n >> 12;
        int pixl = n & 4095;
        int code = fidx[lane];
#pragma unroll
        for (int j = 0; j < 32; j++) {
            int d = wrp + 8 * j;
            float qv  = emb[(size_t)code * 256 + d];
            float zev = ((const float*)&Zsd[d][lane])[0];
            zq_nchw[(((size_t)bimg * 256 + d) << 12) + pixl] = zev + (qv - zev);
        }
    }
}

__global__ void perp_kernel(float* __restrict__ out)
{
    __shared__ float red[512];
    int t = threadIdx.x;
    float p = (float)g_counts[t] * (1.f / 65536.f);
    red[t] = p * logf(p + 1e-10f);
    __syncthreads();
    for (int s = 256; s > 0; s >>= 1) {
        if (t < s) red[t] += red[t + s];
        __syncthreads();
    }
    if (t == 0) out[0] = expf(-red[0]);
}

// ---------------------------------------------------------------------------
extern "C" void kernel_launch(void* const* d_in, const int* in_sizes, int n_in,
                              void* d_out, int out_size)
{
    const float* x      = (const float*)d_in[0];
    const float* w_enc1 = (const float*)d_in[1];
    const float* b_enc1 = (const float*)d_in[2];
    const float* w_enc2 = (const float*)d_in[3];
    const float* b_enc2 = (const float*)d_in[4];
    const float* w_prevq= (const float*)d_in[5];
    const float* b_prevq= (const float*)d_in[6];
    const float* emb    = (const float*)d_in[7];
    const float* w_post = (const float*)d_in[8];
    const float* b_post = (const float*)d_in[9];
    const float* w_dec1 = (const float*)d_in[10];
    const float* b_dec1 = (const float*)d_in[11];
    const float* w_dec2 = (const float*)d_in[12];
    const float* b_dec2 = (const float*)d_in[13];

    float* out  = (float*)d_out;
    float* ze   = out + OFF_ZE;
    float* zq   = out + OFF_ZQ;
    float* perp = out + OFF_PERP;

    void* p;
    cudaGetSymbolAddress(&p, g_h1);       float* h1  = (float*)p;
    cudaGetSymbolAddress(&p, g_h2);       float* h2  = (float*)p;
    cudaGetSymbolAddress(&p, g_zq_nchw);  float* zqn = (float*)p;
    cudaGetSymbolAddress(&p, g_d1);       float* d1  = (float*)p;
    cudaGetSymbolAddress(&p, g_d2);       float* d2  = (float*)p;
    cudaGetSymbolAddress(&p, g_wt_post);  float* wtp = (float*)p;
    cudaGetSymbolAddress(&p, g_wt_dec1);  float* wtd = (float*)p;
    cudaGetSymbolAddress(&p, g_wc1);      float* wc1 = (float*)p;
    cudaGetSymbolAddress(&p, g_wc2);      float* wc2 = (float*)p;
    cudaGetSymbolAddress(&p, g_wc3);      float* wc3 = (float*)p;

    zero_counts_kernel<<<1, 512>>>();
    esq_kernel<<<4, 128>>>(emb);
    repack_conv<3, 64, 4><<<12, 256>>>(w_enc1, wc1);
    repack_conv<64, 128, 4><<<512, 256>>>(w_enc2, wc2);
    repack_conv<128, 256, 3><<<1152, 256>>>(w_prevq, wc3);
    repack_tconv<256, 128><<<2048, 256>>>(w_post, wtp);
    repack_tconv<128, 64><<<512, 256>>>(w_dec1, wtd);

    conv_gemm<3, 64, 4, 2, 1, 256, 256, 128, 128, true, false>
        <<<dim3(256, 1, 16), 256>>>(x, wc1, b_enc1, h1);
    conv_gemm2<64, 128, 4, 2, 1, 128, 128, 64, 64, true, false>
        <<<dim3(32, 1, 16), 256>>>(h1, wc2, b_enc2, h2);
    conv_gemm2<128, 256, 3, 1, 1, 64, 64, 64, 64, false, true>
        <<<dim3(32, 2, 16), 256>>>(h2, wc3, b_prevq, ze);

    vq_kernel<<<2048, 256>>>(ze, emb, zq, zqn);
    perp_kernel<<<1, 512>>>(perp);

    tconv_gemm2<256, 128, 64, 64, false, 128, 128>
        <<<dim3(32, 4, 16), 256>>>(zqn, wtp, b_post, d1);
    tconv_gemm2<128, 64, 128, 128, true, 64, 256>
        <<<dim3(64, 4, 16), 256>>>(d1, wtd, b_dec1, d2);
    dec2_kernel<<<4096, 256>>>(d2, w_dec2, b_dec2, out);
}

// round 14
// speedup vs baseline: 1.5357x; 1.2385x over previous
#include <cuda_runtime.h>
#include <cuda_fp16.h>
#include <math.h>

// ---------------------------------------------------------------------------
// VQ-VAE forward. B=16, D=256, K=512.
// BIT-FROZEN (feeds argmin): enc1/enc2/prevq convs (kw-major ci-fastest,
// single ascending FMA chain; FFMA2 lanes IEEE-exact), VQ (8-acc interleave +
// shuffle-halving combine), z_e / z_q outputs.
// DECODER (x_recon, tolerance 1e-3): post & dec1 on tensor cores
// (mma.sync m16n8k16 fp16 x fp16 -> fp32). dec2 fp32.
// Output: [x_recon 3145728][z_e 16777216][z_q 16777216][perp 1]
// ---------------------------------------------------------------------------

#define OFF_ZE   3145728
#define OFF_ZQ   19922944
#define OFF_PERP 36700160

typedef unsigned long long u64;
typedef unsigned int u32t;

__device__ __forceinline__ void ffma2(u64& acc, u64 a, u64 b)
{
    asm("fma.rn.f32x2 %0, %1, %2, %0;" : "+l"(acc) : "l"(a), "l"(b));
}
__device__ __forceinline__ u64 dup2(float x)
{
    u64 r;
    asm("mov.b64 %0, {%1, %1};" : "=l"(r) : "r"(__float_as_uint(x)));
    return r;
}
__device__ __forceinline__ void unpack2(u64 v, float& lo, float& hi)
{
    unsigned a, b;
    asm("mov.b64 {%0, %1}, %2;" : "=r"(a), "=r"(b) : "l"(v));
    lo = __uint_as_float(a); hi = __uint_as_float(b);
}
__device__ __forceinline__ int pn(int n) { return n + ((n >> 5) << 2); }

__device__ __forceinline__ void mma16816(float* d, const u32t* a, const u32t* b)
{
    asm volatile(
        "mma.sync.aligned.m16n8k16.row.col.f32.f16.f16.f32 "
        "{%0,%1,%2,%3}, {%4,%5,%6,%7}, {%8,%9}, {%0,%1,%2,%3};"
        : "+f"(d[0]), "+f"(d[1]), "+f"(d[2]), "+f"(d[3])
        : "r"(a[0]), "r"(a[1]), "r"(a[2]), "r"(a[3]), "r"(b[0]), "r"(b[1]));
}

// ------------------------- scratch (device globals) -----------------------
__device__ float  g_h1[16 * 64 * 128 * 128];
__device__ float  g_h2[16 * 128 * 64 * 64];
__device__ __half g_zq_h[16 * 256 * 64 * 64];     // decoder input (fp16)
__device__ __half g_d1h[16 * 128 * 128 * 128];    // post out (fp16)
__device__ float  g_d2[16 * 64 * 256 * 256];      // dec1 out (fp32)
__device__ __half g_wt_post_h[4 * 128 * 256 * 4];
__device__ __half g_wt_dec1_h[4 * 64 * 128 * 4];
__device__ float  g_wc1[64 * 48];
__device__ float  g_wc2[128 * 1024];
__device__ float  g_wc3[256 * 1152];
__device__ float  g_esq[512];
__device__ int    g_counts[512];

template <int Cin, int Cout, int KS>
__global__ void repack_conv(const float* __restrict__ w, float* __restrict__ wr)
{
    int idx = blockIdx.x * 256 + threadIdx.x;
    if (idx >= Cout * Cin * KS * KS) return;
    int ci = idx % Cin;
    int t  = idx / Cin;
    int kh = t % KS;
    int t2 = t / KS;
    int kw = t2 % KS;
    int co = t2 / KS;
    wr[idx] = w[((co * Cin + ci) * KS + kh) * KS + kw];
}

// --------------------- 4x4 conv (enc1 only; frozen) ------------------------
template <int Cin, int Cout, int KS, int S, int P,
          int Hin, int Win, int Hout, int Wout, bool RELU, bool NHWC_OUT>
__global__ void __launch_bounds__(256)
conv_gemm(const float* __restrict__ in, const float* __restrict__ w,
          const float* __restrict__ bias, float* __restrict__ out)
{
    constexpr int KK   = Cin * KS * KS;
    constexpr int Npix = Hout * Wout;

    __shared__ float As[16][64];
    __shared__ float Bs[16][64];

    const int t  = threadIdx.x;
    const int n0 = blockIdx.x * 64;
    const int m0 = blockIdx.y * 64;
    const int b  = blockIdx.z;
    const int tm = t >> 4;
    const int tn = t & 15;
    const int ma = t >> 2;
    const int ka = (t & 3) << 2;
    const int nb  = t & 63;
    const int kb0 = t >> 6;

    const int nglob = n0 + nb;
    const int ho_b  = nglob / Wout;
    const int wo_b  = nglob - ho_b * Wout;
    const float* inb = in + (size_t)b * Cin * Hin * Win;

    float acc[4][4];
#pragma unroll
    for (int i = 0; i < 4; i++)
#pragma unroll
        for (int j = 0; j < 4; j++) acc[i][j] = 0.f;

    for (int kb = 0; kb < KK; kb += 16) {
        float4 av = *(const float4*)(w + (size_t)(m0 + ma) * KK + kb + ka);
        float bv[4];
#pragma unroll
        for (int j = 0; j < 4; j++) {
            int kk = kb + kb0 + 4 * j;
            int ci = kk % Cin;
            int r  = kk / Cin;
            int kh = r % KS;
            int kw = r / KS;
            int hi = ho_b * S - P + kh;
            int wi = wo_b * S - P + kw;
            float v = 0.f;
            if (hi >= 0 && hi < Hin && wi >= 0 && wi < Win)
                v = inb[(ci * Hin + hi) * Win + wi];
            bv[j] = v;
        }
        __syncthreads();
        As[ka + 0][ma] = av.x; As[ka + 1][ma] = av.y;
        As[ka + 2][ma] = av.z; As[ka + 3][ma] = av.w;
#pragma unroll
        for (int j = 0; j < 4; j++) Bs[kb0 + 4 * j][nb] = bv[j];
        __syncthreads();

#pragma unroll
        for (int k = 0; k < 16; k++) {
            float4 a  = *(const float4*)&As[k][tm * 4];
            float4 bq = *(const float4*)&Bs[k][tn * 4];
            float ar[4] = {a.x, a.y, a.z, a.w};
            float br[4] = {bq.x, bq.y, bq.z, bq.w};
#pragma unroll
            for (int i = 0; i < 4; i++)
#pragma unroll
                for (int j = 0; j < 4; j++) acc[i][j] += ar[i] * br[j];
        }
    }

#pragma unroll
    for (int i = 0; i < 4; i++) {
        int m = m0 + tm * 4 + i;
        float bb = bias[m];
#pragma unroll
        for (int j = 0; j < 4; j++) {
            float v = acc[i][j] + bb;
            if (RELU) v = fmaxf(v, 0.f);
            int n = n0 + tn * 4 + j;
            if (NHWC_OUT)
                out[((size_t)b * Npix + n) * Cout + m] = v;
            else
                out[((size_t)b * Cout + m) * Npix + n] = v;
        }
    }
}

// ------- 8x8 f32x2 conv, double-buffered (enc2, prevq): bit-frozen ---------
template <int Cin, int Cout, int KS, int S, int P,
          int Hin, int Win, int Hout, int Wout, bool RELU, bool NHWC_OUT>
__global__ void __launch_bounds__(256, 2)
conv_gemm2(const float* __restrict__ in, const float* __restrict__ w,
           const float* __restrict__ bias, float* __restrict__ out)
{
    constexpr int KK   = Cin * KS * KS;
    constexpr int Npix = Hout * Wout;
    constexpr int NT   = KK / 16;

    __shared__ float As[2][16][128];
    __shared__ float Bs[2][16][144];

    const int t  = threadIdx.x;
    const int n0 = blockIdx.x * 128;
    const int m0 = blockIdx.y * 128;
    const int b  = blockIdx.z;
    const int tm = t >> 4;
    const int tn = t & 15;

    const int a_m = t >> 1;
    const int a_k = (t & 1) * 8;
    const int bn  = t & 127;
    const int kk0 = (t >> 7) * 8;
    const int pb  = pn(bn);

    const int nglob = n0 + bn;
    const int ho_b  = nglob / Wout;
    const int wo_b  = nglob - ho_b * Wout;
    const float* inb = in + (size_t)b * Cin * Hin * Win;
    const float* wrow = w + (size_t)(m0 + a_m) * KK + a_k;

    u64 acc[4][8];
#pragma unroll
    for (int p = 0; p < 4; p++)
#pragma unroll
        for (int j = 0; j < 8; j++) acc[p][j] = 0ull;

    const int pnb = pn(tn * 8);

    float4 av0, av1;
    float  bv[8];

#define LOAD_TILE(KB)                                                        \
    {                                                                        \
        av0 = *(const float4*)(wrow + (KB));                                 \
        av1 = *(const float4*)(wrow + (KB) + 4);                             \
        _Pragma("unroll")                                                    \
        for (int i = 0; i < 8; i++) {                                        \
            int kk = (KB) + kk0 + i;                                         \
            int ci = kk % Cin;                                               \
            int r  = kk / Cin;                                               \
            int kh = r % KS;                                                 \
            int kw = r / KS;                                                 \
            int hi = ho_b * S - P + kh;                                      \
            int wi = wo_b * S - P + kw;                                      \
            float v = 0.f;                                                   \
            if (hi >= 0 && hi < Hin && wi >= 0 && wi < Win)                  \
                v = inb[(ci * Hin + hi) * Win + wi];                         \
            bv[i] = v;                                                       \
        }                                                                    \
    }
#define STORE_TILE(BUF)                                                      \
    {                                                                        \
        As[BUF][a_k + 0][a_m] = av0.x; As[BUF][a_k + 1][a_m] = av0.y;        \
        As[BUF][a_k + 2][a_m] = av0.z; As[BUF][a_k + 3][a_m] = av0.w;        \
        As[BUF][a_k + 4][a_m] = av1.x; As[BUF][a_k + 5][a_m] = av1.y;        \
        As[BUF][a_k + 6][a_m] = av1.z; As[BUF][a_k + 7][a_m] = av1.w;        \
        _Pragma("unroll")                                                    \
        for (int i = 0; i < 8; i++) Bs[BUF][kk0 + i][pb] = bv[i];            \
    }

    LOAD_TILE(0);
    STORE_TILE(0);
    __syncthreads();

    for (int it = 0; it < NT; it++) {
        const int cur = it & 1;
        if (it + 1 < NT) LOAD_TILE((it + 1) * 16);

#pragma unroll
        for (int k = 0; k < 16; k++) {
            ulonglong2 ax = *(const ulonglong2*)&As[cur][k][tm * 8];
            ulonglong2 ay = *(const ulonglong2*)&As[cur][k][tm * 8 + 4];
            u64 A[4] = {ax.x, ax.y, ay.x, ay.y};
            float4 b0 = *(const float4*)&Bs[cur][k][pnb];
            float4 b1 = *(const float4*)&Bs[cur][k][pnb + 4];
            u64 bd[8] = {dup2(b0.x), dup2(b0.y), dup2(b0.z), dup2(b0.w),
                         dup2(b1.x), dup2(b1.y), dup2(b1.z), dup2(b1.w)};
#pragma unroll
            for (int p = 0; p < 4; p++)
#pragma unroll
                for (int j = 0; j < 8; j++) ffma2(acc[p][j], A[p], bd[j]);
        }
        if (it + 1 < NT) STORE_TILE(cur ^ 1);
        __syncthreads();
    }
#undef LOAD_TILE
#undef STORE_TILE

#pragma unroll
    for (int p = 0; p < 4; p++) {
        int mlo = m0 + tm * 8 + 2 * p;
        float blo = bias[mlo], bhi = bias[mlo + 1];
#pragma unroll
        for (int j = 0; j < 8; j++) {
            float lo, hi;
            unpack2(acc[p][j], lo, hi);
            float v0 = lo + blo;
            float v1 = hi + bhi;
            if (RELU) { v0 = fmaxf(v0, 0.f); v1 = fmaxf(v1, 0.f); }
            int n = n0 + tn * 8 + j;
            if (NHWC_OUT) {
                out[((size_t)b * Npix + n) * Cout + mlo]     = v0;
                out[((size_t)b * Npix + n) * Cout + mlo + 1] = v1;
            } else {
                out[((size_t)b * Cout + mlo) * Npix + n]       = v0;
                out[((size_t)b * Cout + mlo + 1) * Npix + n]   = v1;
            }
        }
    }
}

// ---------------- tensor-core fp16 convT (post, dec1) ----------------------
// GEMM per parity class: A = weights [Cout x KK], B = im2col input [KK x N].
// mma.sync m16n8k16 f32.f16.f16.f32; 8 warps each computing 32m x 64n.
template <int Cin, int Cout, int Hin, int Win, bool RELU, int BM, int BN,
          bool OUT_HALF>
__global__ void __launch_bounds__(256)
tconv_mma(const __half* __restrict__ in, const __half* __restrict__ wh,
          const float* __restrict__ bias, void* __restrict__ outv)
{
    constexpr int KK   = Cin * 4;
    constexpr int Hout = Hin * 2;
    constexpr int Wout = Win * 2;
    constexpr int NT   = KK / 16;
    constexpr int WM   = BM / 32;          // warps along m (4 or 2)
    constexpr int APT  = BM * 16 / 256;    // A halves per thread (8 or 4)
    constexpr int BPT  = BN * 16 / 256;    // B halves per thread (8 or 16)

    __shared__ __half Ah[2][BM][24];
    __shared__ __half Bh[2][BN][24];

    const int t    = threadIdx.x;
    const int w    = t >> 5;
    const int l    = t & 31;
    const int g    = l >> 2;
    const int tg   = l & 3;
    const int wm   = (w % WM) * 32;
    const int wn   = (w / WM) * 64;

    const int n0   = blockIdx.x * BN;
    const int cls  = blockIdx.y;           // grid.y = 4 (m0 = 0, BM = Cout)
    const int ph   = cls >> 1;
    const int pw   = cls & 1;
    const int b    = blockIdx.z;

    const __half* inb  = in + (size_t)b * Cin * Hin * Win;
    const __half* wcls = wh + (size_t)cls * Cout * KK;

    // staging lanes
    const int a_m = t / (16 / APT);
    const int a_k = (t % (16 / APT)) * APT;
    const int bn  = (BPT == 16) ? t : (t & (BN - 1));
    const int bk0 = (BPT == 16) ? 0 : (t >> 7) * 8;
    const int ng  = n0 + bn;
    const int oy  = ng / Win;
    const int ox  = ng - oy * Win;
    const __half* warow = wcls + (size_t)a_m * KK + a_k;

    float acc[2][8][4];
#pragma unroll
    for (int fm = 0; fm < 2; fm++)
#pragma unroll
        for (int fn = 0; fn < 8; fn++)
#pragma unroll
            for (int q = 0; q < 4; q++) acc[fm][fn][q] = 0.f;

    __half avh[APT];
    __half bvh[BPT];

#define M_LOAD(KB)                                                           \
    {                                                                        \
        _Pragma("unroll")                                                    \
        for (int q = 0; q < APT; q++) avh[q] = warow[(KB) + q];              \
        _Pragma("unroll")                                                    \
        for (int i = 0; i < BPT; i++) {                                      \
            int kk = (KB) + bk0 + i;                                         \
            int ci = kk >> 2;                                                \
            int tt = kk & 3;                                                 \
            int ty = tt >> 1;                                                \
            int tx = tt & 1;                                                 \
            int hi = oy + ph - ty;                                           \
            int wi = ox + pw - tx;                                           \
            __half v = __ushort_as_half((unsigned short)0);                  \
            if (hi >= 0 && hi < Hin && wi >= 0 && wi < Win)                  \
                v = inb[(ci * Hin + hi) * Win + wi];                         \
            bvh[i] = v;                                                      \
        }                                                                    \
    }
#define M_STORE(BUF)                                                         \
    {                                                                        \
        _Pragma("unroll")                                                    \
        for (int q = 0; q < APT; q++) Ah[BUF][a_m][a_k + q] = avh[q];        \
        _Pragma("unroll")                                                    \
        for (int i = 0; i < BPT; i++) Bh[BUF][bn][bk0 + i] = bvh[i];         \
    }

    M_LOAD(0);
    M_STORE(0);
    __syncthreads();

    for (int it = 0; it < NT; it++) {
        const int cur = it & 1;
        if (it + 1 < NT) M_LOAD((it + 1) * 16);

        u32t afr[2][4];
#pragma unroll
        for (int fm = 0; fm < 2; fm++) {
            int r = wm + fm * 16 + g;
            afr[fm][0] = *(const u32t*)&Ah[cur][r][2 * tg];
            afr[fm][1] = *(const u32t*)&Ah[cur][r + 8][2 * tg];
            afr[fm][2] = *(const u32t*)&Ah[cur][r][2 * tg + 8];
            afr[fm][3] = *(const u32t*)&Ah[cur][r + 8][2 * tg + 8];
        }
#pragma unroll
        for (int fn = 0; fn < 8; fn++) {
            int nn = wn + fn * 8 + g;
            u32t bfr[2];
            bfr[0] = *(const u32t*)&Bh[cur][nn][2 * tg];
            bfr[1] = *(const u32t*)&Bh[cur][nn][2 * tg + 8];
#pragma unroll
            for (int fm = 0; fm < 2; fm++)
                mma16816(acc[fm][fn], afr[fm], bfr);
        }

        if (it + 1 < NT) M_STORE(cur ^ 1);
        __syncthreads();
    }
#undef M_LOAD
#undef M_STORE

    // epilogue: scatter to NCHW parity grid
    __half* outh = (__half*)outv;
    float*  outf = (float*)outv;
#pragma unroll
    for (int fm = 0; fm < 2; fm++) {
        int rA = wm + fm * 16 + g;
        int rB = rA + 8;
        float bA = bias[rA], bB = bias[rB];
#pragma unroll
        for (int fn = 0; fn < 8; fn++) {
            int nc = n0 + wn + fn * 8 + 2 * tg;
#pragma unroll
            for (int e = 0; e < 2; e++) {
                int n  = nc + e;
                int yy = n / Win;
                int xx = n - yy * Win;
                int ho = 2 * yy + ph;
                int wo = 2 * xx + pw;
                float vA = acc[fm][fn][e] + bA;
                float vB = acc[fm][fn][2 + e] + bB;
                if (RELU) { vA = fmaxf(vA, 0.f); vB = fmaxf(vB, 0.f); }
                size_t oA = (((size_t)b * Cout + rA) * Hout + ho) * Wout + wo;
                size_t oB = (((size_t)b * Cout + rB) * Hout + ho) * Wout + wo;
                if (OUT_HALF) {
                    outh[oA] = __float2half_rn(vA);
                    outh[oB] = __float2half_rn(vB);
                } else {
                    outf[oA] = vA;
                    outf[oB] = vB;
                }
            }
        }
    }
}

// Repack convT weights to fp16: wt[class][co][ci*4 + ty*2+tx]
template <int Cin, int Cout>
__global__ void repack_tconv_h(const float* __restrict__ w, __half* __restrict__ wt)
{
    int idx = blockIdx.x * 256 + threadIdx.x;
    if (idx >= Cin * Cout * 16) return;
    int tt  = idx & 3;
    int t2  = idx >> 2;
    int ci  = t2 % Cin;
    int t3  = t2 / Cin;
    int co  = t3 % Cout;
    int cls = t3 / Cout;
    int ph = cls >> 1, pw = cls & 1;
    int ty = tt >> 1,  tx = tt & 1;
    int kh = ph ? (ty ? 2 : 0) : (ty ? 3 : 1);
    int kw = pw ? (tx ? 2 : 0) : (tx ? 3 : 1);
    wt[idx] = __float2half_rn(w[((ci * Cout + co) * 4 + kh) * 4 + kw]);
}

__global__ void __launch_bounds__(256)
dec2_kernel(const float* __restrict__ in, const float* __restrict__ w,
            const float* __restrict__ bias, float* __restrict__ out)
{
    __shared__ float ws[3 * 64 * 9];
    for (int i = threadIdx.x; i < 3 * 64 * 9; i += 256) {
        int q  = i % 9;
        int ci = (i / 9) % 64;
        int co = i / (9 * 64);
        int kh = q / 3, kw = q % 3;
        ws[i] = w[((ci * 3 + co) * 3 + (2 - kh)) * 3 + (2 - kw)];
    }
    __syncthreads();

    int pix = blockIdx.x * 256 + threadIdx.x;
    int b  = pix >> 16;
    int p  = pix & 65535;
    int ho = p >> 8;
    int wo = p & 255;
    float a0 = bias[0], a1 = bias[1], a2 = bias[2];
    const float* inb = in + (size_t)b * 64 * 65536;
    for (int ci = 0; ci < 64; ci++) {
        float r[9];
#pragma unroll
        for (int kh = 0; kh < 3; kh++)
#pragma unroll
            for (int kw = 0; kw < 3; kw++) {
                int hi = ho - 1 + kh, wi = wo - 1 + kw;
                r[kh * 3 + kw] = (hi >= 0 && hi < 256 && wi >= 0 && wi < 256)
                                     ? inb[ci * 65536 + hi * 256 + wi] : 0.f;
            }
#pragma unroll
        for (int q = 0; q < 9; q++) {
            a0 += r[q] * ws[0 * 576 + ci * 9 + q];
            a1 += r[q] * ws[1 * 576 + ci * 9 + q];
            a2 += r[q] * ws[2 * 576 + ci * 9 + q];
        }
    }
    out[(b * 3 + 0) * 65536 + p] = a0;
    out[(b * 3 + 1) * 65536 + p] = a1;
    out[(b * 3 + 2) * 65536 + p] = a2;
}

// ------------------------------- VQ (bit-frozen) ---------------------------
__global__ void zero_counts_kernel() { g_counts[threadIdx.x] = 0; }

__global__ void esq_kernel(const float* __restrict__ emb)
{
    int k = blockIdx.x * 128 + threadIdx.x;
    if (k < 512) {
        const float4* e = (const float4*)(emb + (size_t)k * 256);
        float s = 0.f;
#pragma unroll
        for (int i = 0; i < 64; i++) {
            float4 v = e[i];
            s += v.x * v.x + v.y * v.y + v.z * v.z + v.w * v.w;
        }
        g_esq[k] = s;
    }
}

__global__ void __launch_bounds__(256)
vq_kernel(const float* __restrict__ ze, const float* __restrict__ emb,
          float* __restrict__ zq_nhwc, __half* __restrict__ zq_h)
{
    __shared__ u64   Zsd[256][32];
    __shared__ float Es[32][64];
    __shared__ float zpart[32][8];
    __shared__ float zsqs[32];
    __shared__ float rbest[32][16];
    __shared__ int   rk[32][16];
    __shared__ int   fidx[32];

    const int t  = threadIdx.x;
    const int n0 = blockIdx.x * 32;
    const int tm = t >> 4;
    const int tn = t & 15;
    const int r0 = tm * 2, r1 = tm * 2 + 1;

#pragma unroll
    for (int j = 0; j < 8; j++) {
        int idx = t + 256 * j;
        int m   = idx >> 6;
        int kq  = idx & 63;
        float4 v = *(const float4*)(ze + ((size_t)(n0 + m)) * 256 + kq * 4);
        Zsd[kq * 4 + 0][m] = dup2(v.x); Zsd[kq * 4 + 1][m] = dup2(v.y);
        Zsd[kq * 4 + 2][m] = dup2(v.z); Zsd[kq * 4 + 3][m] = dup2(v.w);
    }
    __syncthreads();

    {
        int row = t & 31;
        int seg = t >> 5;
        float s = 0.f;
#pragma unroll
        for (int i = 0; i < 32; i++) {
            float v = ((const float*)&Zsd[seg * 32 + i][row])[0];
            s += v * v;
        }
        zpart[row][seg] = s;
    }
    __syncthreads();
    if (t < 32) {
        float s = zpart[t][0];
#pragma unroll
        for (int q = 1; q < 8; q++) s += zpart[t][q];
        zsqs[t] = s;
    }
    __syncthreads();

    const float zr0 = zsqs[r0];
    const float zr1 = zsqs[r1];

    float best[2] = {1e30f, 1e30f};
    int   bk[2]   = {0, 0};

    for (int e0 = 0; e0 < 512; e0 += 64) {
        u64 accP[8][2][2];
#pragma unroll
        for (int l = 0; l < 8; l++)
#pragma unroll
            for (int i = 0; i < 2; i++)
#pragma unroll
                for (int cp = 0; cp < 2; cp++) accP[l][i][cp] = 0ull;

        for (int kb = 0; kb < 256; kb += 32) {
            __syncthreads();
#pragma unroll
            for (int j = 0; j < 2; j++) {
                int idx = t + 256 * j;
                int e   = idx >> 3;
                int k4  = (idx & 7) * 4;
                float4 v = *(const float4*)(emb + (size_t)(e0 + e) * 256 + kb + k4);
                Es[k4 + 0][e] = v.x; Es[k4 + 1][e] = v.y;
                Es[k4 + 2][e] = v.z; Es[k4 + 3][e] = v.w;
            }
            __syncthreads();
#pragma unroll
            for (int k = 0; k < 32; k++) {
                const int l = k & 7;
                u64 A0 = Zsd[kb + k][r0];
                u64 A1 = Zsd[kb + k][r1];
                ulonglong2 B = *(const ulonglong2*)&Es[k][tn * 4];
                ffma2(accP[l][0][0], A0, B.x);
                ffma2(accP[l][0][1], A0, B.y);
                ffma2(accP[l][1][0], A1, B.x);
                ffma2(accP[l][1][1], A1, B.y);
            }
        }
#pragma unroll
        for (int i = 0; i < 2; i++) {
            float zr = (i == 0) ? zr0 : zr1;
#pragma unroll
            for (int cp = 0; cp < 2; cp++) {
                float v0[8], v1[8];
#pragma unroll
                for (int l = 0; l < 8; l++) unpack2(accP[l][i][cp], v0[l], v1[l]);
                {
                    float q0 = __fadd_rn(v0[0], v0[4]);
                    float q1 = __fadd_rn(v0[1], v0[5]);
                    float q2 = __fadd_rn(v0[2], v0[6]);
                    float q3 = __fadd_rn(v0[3], v0[7]);
                    float d  = __fadd_rn(__fadd_rn(q0, q2), __fadd_rn(q1, q3));
                    int kcode = e0 + tn * 4 + 2 * cp;
                    float eq = g_esq[kcode];
                    float s = __fadd_rn(__fadd_rn(zr, eq), -__fmul_rn(2.f, d));
                    if (s < best[i]) { best[i] = s; bk[i] = kcode; }
                }
                {
                    float q0 = __fadd_rn(v1[0], v1[4]);
                    float q1 = __fadd_rn(v1[1], v1[5]);
                    float q2 = __fadd_rn(v1[2], v1[6]);
                    float q3 = __fadd_rn(v1[3], v1[7]);
                    float d  = __fadd_rn(__fadd_rn(q0, q2), __fadd_rn(q1, q3));
                    int kcode = e0 + tn * 4 + 2 * cp + 1;
                    float eq = g_esq[kcode];
                    float s = __fadd_rn(__fadd_rn(zr, eq), -__fmul_rn(2.f, d));
                    if (s < best[i]) { best[i] = s; bk[i] = kcode; }
                }
            }
        }
    }
    __syncthreads();
    rbest[r0][tn] = best[0]; rk[r0][tn] = bk[0];
    rbest[r1][tn] = best[1]; rk[r1][tn] = bk[1];
    __syncthreads();
    if (t < 32) {
        float bs = rbest[t][0];
        int   bi = rk[t][0];
#pragma unroll
        for (int q = 1; q < 16; q++) {
            float s = rbest[t][q];
            int   k = rk[t][q];
            if (s < bs || (s == bs && k < bi)) { bs = s; bi = k; }
        }
        fidx[t] = bi;
        atomicAdd(&g_counts[bi], 1);
    }
    __syncthreads();

#pragma unroll
    for (int j = 0; j < 8; j++) {
        int idx = t + 256 * j;
        int m   = idx >> 6;
        int d4  = idx & 63;
        float4 v = *(const float4*)(emb + (size_t)fidx[m] * 256 + d4 * 4);
        *(float4*)(zq_nhwc + ((size_t)(n0 + m)) * 256 + d4 * 4) = v;
    }
    {
        int lane = t & 31, wrp = t >> 5;
        int n    = n0 + lane;
        int bimg = n >> 12;
        int pixl = n & 4095;
        int code = fidx[lane];
#pragma unroll
        for (int j = 0; j < 32; j++) {
            int d = wrp + 8 * j;
            float qv  = emb[(size_t)code * 256 + d];
            float zev = ((const float*)&Zsd[d][lane])[0];
            float dec = zev + (qv - zev);
            zq_h[(((size_t)bimg * 256 + d) << 12) + pixl] = __float2half_rn(dec);
        }
    }
}

__global__ void perp_kernel(float* __restrict__ out)
{
    __shared__ float red[512];
    int t = threadIdx.x;
    float p = (float)g_counts[t] * (1.f / 65536.f);
    red[t] = p * logf(p + 1e-10f);
    __syncthreads();
    for (int s = 256; s > 0; s >>= 1) {
        if (t < s) red[t] += red[t + s];
        __syncthreads();
    }
    if (t == 0) out[0] = expf(-red[0]);
}

// ---------------------------------------------------------------------------
extern "C" void kernel_launch(void* const* d_in, const int* in_sizes, int n_in,
                              void* d_out, int out_size)
{
    const float* x      = (const float*)d_in[0];
    const float* w_enc1 = (const float*)d_in[1];
    const float* b_enc1 = (const float*)d_in[2];
    const float* w_enc2 = (const float*)d_in[3];
    const float* b_enc2 = (const float*)d_in[4];
    const float* w_prevq= (const float*)d_in[5];
    const float* b_prevq= (const float*)d_in[6];
    const float* emb    = (const float*)d_in[7];
    const float* w_post = (const float*)d_in[8];
    const float* b_post = (const float*)d_in[9];
    const float* w_dec1 = (const float*)d_in[10];
    const float* b_dec1 = (const float*)d_in[11];
    const float* w_dec2 = (const float*)d_in[12];
    const float* b_dec2 = (const float*)d_in[13];

    float* out  = (float*)d_out;
    float* ze   = out + OFF_ZE;
    float* zq   = out + OFF_ZQ;
    float* perp = out + OFF_PERP;

    void* p;
    cudaGetSymbolAddress(&p, g_h1);        float*  h1   = (float*)p;
    cudaGetSymbolAddress(&p, g_h2);        float*  h2   = (float*)p;
    cudaGetSymbolAddress(&p, g_zq_h);      __half* zqh  = (__half*)p;
    cudaGetSymbolAddress(&p, g_d1h);       __half* d1h  = (__half*)p;
    cudaGetSymbolAddress(&p, g_d2);        float*  d2   = (float*)p;
    cudaGetSymbolAddress(&p, g_wt_post_h); __half* wtph = (__half*)p;
    cudaGetSymbolAddress(&p, g_wt_dec1_h); __half* wtdh = (__half*)p;
    cudaGetSymbolAddress(&p, g_wc1);       float*  wc1  = (float*)p;
    cudaGetSymbolAddress(&p, g_wc2);       float*  wc2  = (float*)p;
    cudaGetSymbolAddress(&p, g_wc3);       float*  wc3  = (float*)p;

    zero_counts_kernel<<<1, 512>>>();
    esq_kernel<<<4, 128>>>(emb);
    repack_conv<3, 64, 4><<<12, 256>>>(w_enc1, wc1);
    repack_conv<64, 128, 4><<<512, 256>>>(w_enc2, wc2);
    repack_conv<128, 256, 3><<<1152, 256>>>(w_prevq, wc3);
    repack_tconv_h<256, 128><<<2048, 256>>>(w_post, wtph);
    repack_tconv_h<128, 64><<<512, 256>>>(w_dec1, wtdh);

    // encoder (bit-frozen)
    conv_gemm<3, 64, 4, 2, 1, 256, 256, 128, 128, true, false>
        <<<dim3(256, 1, 16), 256>>>(x, wc1, b_enc1, h1);
    conv_gemm2<64, 128, 4, 2, 1, 128, 128, 64, 64, true, false>
        <<<dim3(32, 1, 16), 256>>>(h1, wc2, b_enc2, h2);
    conv_gemm2<128, 256, 3, 1, 1, 64, 64, 64, 64, false, true>
        <<<dim3(32, 2, 16), 256>>>(h2, wc3, b_prevq, ze);

    vq_kernel<<<2048, 256>>>(ze, emb, zq, zqh);
    perp_kernel<<<1, 512>>>(perp);

    // decoder (tensor-core fp16, tolerance path)
    tconv_mma<256, 128, 64, 64, false, 128, 128, true>
        <<<dim3(32, 4, 16), 256>>>(zqh, wtph, b_post, d1h);
    tconv_mma<128, 64, 128, 128, true, 64, 256, false>
        <<<dim3(64, 4, 16), 256>>>(d1h, wtdh, b_dec1, d2);
    dec2_kernel<<<4096, 256>>>(d2, w_dec2, b_dec2, out);
}

// round 16
// speedup vs baseline: 2.0423x; 1.3299x over previous
#include <cuda_runtime.h>
#include <cuda_fp16.h>
#include <math.h>

// ---------------------------------------------------------------------------
// VQ-VAE forward. B=16, D=256, K=512.
// BIT-FROZEN: enc1/enc2/prevq convs, VQ argmin, z_e / z_q outputs.
// DECODER (tolerance 1e-3): post & dec1 via mma.sync m16n8k16 (fp16->fp32),
// NHWC fp16 dataflow, tt-major k-order, vectorized staging; dec2 halo-smem.
// Output: [x_recon 3145728][z_e 16777216][z_q 16777216][perp 1]
// ---------------------------------------------------------------------------

#define OFF_ZE   3145728
#define OFF_ZQ   19922944
#define OFF_PERP 36700160

typedef unsigned long long u64;
typedef unsigned int u32t;

__device__ __forceinline__ void ffma2(u64& acc, u64 a, u64 b)
{
    asm("fma.rn.f32x2 %0, %1, %2, %0;" : "+l"(acc) : "l"(a), "l"(b));
}
__device__ __forceinline__ u64 dup2(float x)
{
    u64 r;
    asm("mov.b64 %0, {%1, %1};" : "=l"(r) : "r"(__float_as_uint(x)));
    return r;
}
__device__ __forceinline__ void unpack2(u64 v, float& lo, float& hi)
{
    unsigned a, b;
    asm("mov.b64 {%0, %1}, %2;" : "=r"(a), "=r"(b) : "l"(v));
    lo = __uint_as_float(a); hi = __uint_as_float(b);
}
__device__ __forceinline__ int pn(int n) { return n + ((n >> 5) << 2); }

__device__ __forceinline__ void mma16816(float* d, const u32t* a, const u32t* b)
{
    asm volatile(
        "mma.sync.aligned.m16n8k16.row.col.f32.f16.f16.f32 "
        "{%0,%1,%2,%3}, {%4,%5,%6,%7}, {%8,%9}, {%0,%1,%2,%3};"
        : "+f"(d[0]), "+f"(d[1]), "+f"(d[2]), "+f"(d[3])
        : "r"(a[0]), "r"(a[1]), "r"(a[2]), "r"(a[3]), "r"(b[0]), "r"(b[1]));
}

// ------------------------- scratch (device globals) -----------------------
__device__ float  g_h1[16 * 64 * 128 * 128];
__device__ float  g_h2[16 * 128 * 64 * 64];
__device__ __half g_zq_h[16 * 4096 * 256];     // dec_in NHWC fp16
__device__ __half g_d1h[16 * 16384 * 128];     // post out NHWC fp16
__device__ __half g_d2h[16 * 65536 * 64];      // dec1 out NHWC fp16
__device__ __half g_wt2_post[4 * 128 * 1024];  // [cls][co][tt*Cin+ci] fp16
__device__ __half g_wt2_dec1[4 * 64 * 512];
__device__ float  g_wc1[64 * 48];
__device__ float  g_wc2[128 * 1024];
__device__ float  g_wc3[256 * 1152];
__device__ float  g_esq[512];
__device__ int    g_counts[512];

template <int Cin, int Cout, int KS>
__global__ void repack_conv(const float* __restrict__ w, float* __restrict__ wr)
{
    int idx = blockIdx.x * 256 + threadIdx.x;
    if (idx >= Cout * Cin * KS * KS) return;
    int ci = idx % Cin;
    int t  = idx / Cin;
    int kh = t % KS;
    int t2 = t / KS;
    int kw = t2 % KS;
    int co = t2 / KS;
    wr[idx] = w[((co * Cin + ci) * KS + kh) * KS + kw];
}

// tconv weights -> fp16, k' = tt*Cin + ci per parity class
template <int Cin, int Cout>
__global__ void repack_t05(const float* __restrict__ w, __half* __restrict__ wt)
{
    int idx = blockIdx.x * 256 + threadIdx.x;
    if (idx >= 4 * Cout * Cin * 4) return;
    constexpr int K = Cin * 4;
    int kp  = idx % K;
    int co  = (idx / K) % Cout;
    int cls = idx / (K * Cout);
    int tt  = kp / Cin;
    int ci  = kp % Cin;
    int ph = cls >> 1, pw = cls & 1;
    int ty = tt >> 1,  tx = tt & 1;
    int kh = ph ? (ty ? 2 : 0) : (ty ? 3 : 1);
    int kw = pw ? (tx ? 2 : 0) : (tx ? 3 : 1);
    wt[idx] = __float2half_rn(w[((ci * Cout + co) * 4 + kh) * 4 + kw]);
}

// --------------------- 4x4 conv (enc1; bit-frozen) -------------------------
template <int Cin, int Cout, int KS, int S, int P,
          int Hin, int Win, int Hout, int Wout, bool RELU, bool NHWC_OUT>
__global__ void __launch_bounds__(256)
conv_gemm(const float* __restrict__ in, const float* __restrict__ w,
          const float* __restrict__ bias, float* __restrict__ out)
{
    constexpr int KK   = Cin * KS * KS;
    constexpr int Npix = Hout * Wout;

    __shared__ float As[16][64];
    __shared__ float Bs[16][64];

    const int t  = threadIdx.x;
    const int n0 = blockIdx.x * 64;
    const int m0 = blockIdx.y * 64;
    const int b  = blockIdx.z;
    const int tm = t >> 4;
    const int tn = t & 15;
    const int ma = t >> 2;
    const int ka = (t & 3) << 2;
    const int nb  = t & 63;
    const int kb0 = t >> 6;

    const int nglob = n0 + nb;
    const int ho_b  = nglob / Wout;
    const int wo_b  = nglob - ho_b * Wout;
    const float* inb = in + (size_t)b * Cin * Hin * Win;

    float acc[4][4];
#pragma unroll
    for (int i = 0; i < 4; i++)
#pragma unroll
        for (int j = 0; j < 4; j++) acc[i][j] = 0.f;

    for (int kb = 0; kb < KK; kb += 16) {
        float4 av = *(const float4*)(w + (size_t)(m0 + ma) * KK + kb + ka);
        float bv[4];
#pragma unroll
        for (int j = 0; j < 4; j++) {
            int kk = kb + kb0 + 4 * j;
            int ci = kk % Cin;
            int r  = kk / Cin;
            int kh = r % KS;
            int kw = r / KS;
            int hi = ho_b * S - P + kh;
            int wi = wo_b * S - P + kw;
            float v = 0.f;
            if (hi >= 0 && hi < Hin && wi >= 0 && wi < Win)
                v = inb[(ci * Hin + hi) * Win + wi];
            bv[j] = v;
        }
        __syncthreads();
        As[ka + 0][ma] = av.x; As[ka + 1][ma] = av.y;
        As[ka + 2][ma] = av.z; As[ka + 3][ma] = av.w;
#pragma unroll
        for (int j = 0; j < 4; j++) Bs[kb0 + 4 * j][nb] = bv[j];
        __syncthreads();

#pragma unroll
        for (int k = 0; k < 16; k++) {
            float4 a  = *(const float4*)&As[k][tm * 4];
            float4 bq = *(const float4*)&Bs[k][tn * 4];
            float ar[4] = {a.x, a.y, a.z, a.w};
            float br[4] = {bq.x, bq.y, bq.z, bq.w};
#pragma unroll
            for (int i = 0; i < 4; i++)
#pragma unroll
                for (int j = 0; j < 4; j++) acc[i][j] += ar[i] * br[j];
        }
    }

#pragma unroll
    for (int i = 0; i < 4; i++) {
        int m = m0 + tm * 4 + i;
        float bb = bias[m];
#pragma unroll
        for (int j = 0; j < 4; j++) {
            float v = acc[i][j] + bb;
            if (RELU) v = fmaxf(v, 0.f);
            int n = n0 + tn * 4 + j;
            if (NHWC_OUT)
                out[((size_t)b * Npix + n) * Cout + m] = v;
            else
                out[((size_t)b * Cout + m) * Npix + n] = v;
        }
    }
}

// ------- 8x8 f32x2 conv, double-buffered (enc2, prevq): bit-frozen ---------
template <int Cin, int Cout, int KS, int S, int P,
          int Hin, int Win, int Hout, int Wout, bool RELU, bool NHWC_OUT>
__global__ void __launch_bounds__(256, 2)
conv_gemm2(const float* __restrict__ in, const float* __restrict__ w,
           const float* __restrict__ bias, float* __restrict__ out)
{
    constexpr int KK   = Cin * KS * KS;
    constexpr int Npix = Hout * Wout;
    constexpr int NT   = KK / 16;

    __shared__ float As[2][16][128];
    __shared__ float Bs[2][16][144];

    const int t  = threadIdx.x;
    const int n0 = blockIdx.x * 128;
    const int m0 = blockIdx.y * 128;
    const int b  = blockIdx.z;
    const int tm = t >> 4;
    const int tn = t & 15;

    const int a_m = t >> 1;
    const int a_k = (t & 1) * 8;
    const int bn  = t & 127;
    const int kk0 = (t >> 7) * 8;
    const int pb  = pn(bn);

    const int nglob = n0 + bn;
    const int ho_b  = nglob / Wout;
    const int wo_b  = nglob - ho_b * Wout;
    const float* inb = in + (size_t)b * Cin * Hin * Win;
    const float* wrow = w + (size_t)(m0 + a_m) * KK + a_k;

    u64 acc[4][8];
#pragma unroll
    for (int p = 0; p < 4; p++)
#pragma unroll
        for (int j = 0; j < 8; j++) acc[p][j] = 0ull;

    const int pnb = pn(tn * 8);

    float4 av0, av1;
    float  bv[8];

#define LOAD_TILE(KB)                                                        \
    {                                                                        \
        av0 = *(const float4*)(wrow + (KB));                                 \
        av1 = *(const float4*)(wrow + (KB) + 4);                             \
        _Pragma("unroll")                                                    \
        for (int i = 0; i < 8; i++) {                                        \
            int kk = (KB) + kk0 + i;                                         \
            int ci = kk % Cin;                                               \
            int r  = kk / Cin;                                               \
            int kh = r % KS;                                                 \
            int kw = r / KS;                                                 \
            int hi = ho_b * S - P + kh;                                      \
            int wi = wo_b * S - P + kw;                                      \
            float v = 0.f;                                                   \
            if (hi >= 0 && hi < Hin && wi >= 0 && wi < Win)                  \
                v = inb[(ci * Hin + hi) * Win + wi];                         \
            bv[i] = v;                                                       \
        }                                                                    \
    }
#define STORE_TILE(BUF)                                                      \
    {                                                                        \
        As[BUF][a_k + 0][a_m] = av0.x; As[BUF][a_k + 1][a_m] = av0.y;        \
        As[BUF][a_k + 2][a_m] = av0.z; As[BUF][a_k + 3][a_m] = av0.w;        \
        As[BUF][a_k + 4][a_m] = av1.x; As[BUF][a_k + 5][a_m] = av1.y;        \
        As[BUF][a_k + 6][a_m] = av1.z; As[BUF][a_k + 7][a_m] = av1.w;        \
        _Pragma("unroll")                                                    \
        for (int i = 0; i < 8; i++) Bs[BUF][kk0 + i][pb] = bv[i];            \
    }

    LOAD_TILE(0);
    STORE_TILE(0);
    __syncthreads();

    for (int it = 0; it < NT; it++) {
        const int cur = it & 1;
        if (it + 1 < NT) LOAD_TILE((it + 1) * 16);

#pragma unroll
        for (int k = 0; k < 16; k++) {
            ulonglong2 ax = *(const ulonglong2*)&As[cur][k][tm * 8];
            ulonglong2 ay = *(const ulonglong2*)&As[cur][k][tm * 8 + 4];
            u64 A[4] = {ax.x, ax.y, ay.x, ay.y};
            float4 b0 = *(const float4*)&Bs[cur][k][pnb];
            float4 b1 = *(const float4*)&Bs[cur][k][pnb + 4];
            u64 bd[8] = {dup2(b0.x), dup2(b0.y), dup2(b0.z), dup2(b0.w),
                         dup2(b1.x), dup2(b1.y), dup2(b1.z), dup2(b1.w)};
#pragma unroll
            for (int p = 0; p < 4; p++)
#pragma unroll
                for (int j = 0; j < 8; j++) ffma2(acc[p][j], A[p], bd[j]);
        }
        if (it + 1 < NT) STORE_TILE(cur ^ 1);
        __syncthreads();
    }
#undef LOAD_TILE
#undef STORE_TILE

#pragma unroll
    for (int p = 0; p < 4; p++) {
        int mlo = m0 + tm * 8 + 2 * p;
        float blo = bias[mlo], bhi = bias[mlo + 1];
#pragma unroll
        for (int j = 0; j < 8; j++) {
            float lo, hi;
            unpack2(acc[p][j], lo, hi);
            float v0 = lo + blo;
            float v1 = hi + bhi;
            if (RELU) { v0 = fmaxf(v0, 0.f); v1 = fmaxf(v1, 0.f); }
            int n = n0 + tn * 8 + j;
            if (NHWC_OUT) {
                out[((size_t)b * Npix + n) * Cout + mlo]     = v0;
                out[((size_t)b * Npix + n) * Cout + mlo + 1] = v1;
            } else {
                out[((size_t)b * Cout + mlo) * Npix + n]       = v0;
                out[((size_t)b * Cout + mlo + 1) * Npix + n]   = v1;
            }
        }
    }
}

// --------- mma.sync fp16 convT (post, dec1), NHWC, tt-major k --------------
// D[M=BPIX pixels, N=Cout] = A[pix,K] * B[cout,K]^T  per parity class.
// 8 warps: WPIX = BPIX/32 pixel-rows x (8/WPIX) cout-cols (64 cout each).
template <int Cin, int Cout, int Hin, int Win, bool RELU, int BPIX>
__global__ void __launch_bounds__(256)
tconv_mma(const __half* __restrict__ in, const __half* __restrict__ wt,
          const float* __restrict__ bias, __half* __restrict__ outh)
{
    constexpr int K     = Cin * 4;
    constexpr int NT    = K / 16;
    constexpr int Hout  = Hin * 2;
    constexpr int Wout  = Win * 2;
    constexpr int NpixI = Hin * Win;
    constexpr int NpixO = Hout * Wout;
    constexpr int WPIX  = BPIX / 32;
    constexpr int APU   = BPIX * 2 / 256;       // A uint4 per thread (1 or 2)
    constexpr int BPU   = Cout * 2 / 128;       // B uint4 per 128 thr (2 or 1)

    __shared__ __half Ah[2][BPIX][24];
    __shared__ __half Bh[2][Cout][24];

    const int t   = threadIdx.x;
    const int wid = t >> 5;
    const int l   = t & 31;
    const int g   = l >> 2;
    const int tg  = l & 3;
    const int wpr = (wid % WPIX) * 32;
    const int wpc = (wid / WPIX) * 64;

    const int n0  = blockIdx.x * BPIX;
    const int cls = blockIdx.y;
    const int ph  = cls >> 1;
    const int pw  = cls & 1;
    const int b   = blockIdx.z;

    const __half* inb = in + (size_t)b * NpixI * Cin;
    const __half* wcl = wt + (size_t)cls * Cout * K;

    // A staging geometry (pixel fixed per (i,t))
    int aoy[APU], aox[APU], aseg[APU];
#pragma unroll
    for (int i = 0; i < APU; i++) {
        int u   = i * 256 + t;
        int row = u >> 1;
        aseg[i] = (u & 1) * 8;
        int pix = n0 + row;
        aoy[i]  = pix / Win;
        aox[i]  = pix - aoy[i] * Win;
    }
    // B staging: u = t (and t-128 handled via loop over BPU on t<128*BPU)
    float acc[2][8][4];
#pragma unroll
    for (int fm = 0; fm < 2; fm++)
#pragma unroll
        for (int fn = 0; fn < 8; fn++)
#pragma unroll
            for (int q = 0; q < 4; q++) acc[fm][fn][q] = 0.f;

    uint4 av[APU];
    uint4 bv2[2];
    int   nb_cnt;   // B uint4 this thread stages (per chunk)

#define M_LOAD(KB)                                                           \
    {                                                                        \
        const int tt  = (KB) / Cin;                                          \
        const int cib = (KB) - tt * Cin;                                     \
        const int ty = tt >> 1, tx = tt & 1;                                 \
        _Pragma("unroll")                                                    \
        for (int i = 0; i < APU; i++) {                                      \
            int hi = aoy[i] + ph - ty;                                       \
            int wi = aox[i] + pw - tx;                                       \
            uint4 v = make_uint4(0, 0, 0, 0);                                \
            if (hi >= 0 && hi < Hin && wi >= 0 && wi < Win)                  \
                v = *(const uint4*)(inb + ((size_t)(hi * Win + wi)) * Cin    \
                                    + cib + aseg[i]);                        \
            av[i] = v;                                                       \
        }                                                                    \
        nb_cnt = 0;                                                          \
        _Pragma("unroll")                                                    \
        for (int i = 0; i < 2; i++) {                                        \
            int u = i * 256 + t;                                             \
            if (u < Cout * 2) {                                              \
                int co = u >> 1;                                             \
                int sg = (u & 1) * 8;                                        \
                bv2[nb_cnt++] = *(const uint4*)(wcl + (size_t)co * K + (KB) + sg); \
            }                                                                \
        }                                                                    \
    }
#define M_STORE(BUF)                                                         \
    {                                                                        \
        _Pragma("unroll")                                                    \
        for (int i = 0; i < APU; i++) {                                      \
            int u = i * 256 + t;                                             \
            *(uint4*)&Ah[BUF][u >> 1][(u & 1) * 8] = av[i];                  \
        }                                                                    \
        int c = 0;                                                           \
        _Pragma("unroll")                                                    \
        for (int i = 0; i < 2; i++) {                                        \
            int u = i * 256 + t;                                             \
            if (u < Cout * 2)                                                \
                *(uint4*)&Bh[BUF][u >> 1][(u & 1) * 8] = bv2[c++];           \
        }                                                                    \
    }

    M_LOAD(0);
    M_STORE(0);
    __syncthreads();

    for (int it = 0; it < NT; it++) {
        const int cur = it & 1;
        if (it + 1 < NT) M_LOAD((it + 1) * 16);

        u32t afr[2][4];
#pragma unroll
        for (int fm = 0; fm < 2; fm++) {
            int r = wpr + fm * 16 + g;
            afr[fm][0] = *(const u32t*)&Ah[cur][r][2 * tg];
            afr[fm][1] = *(const u32t*)&Ah[cur][r + 8][2 * tg];
            afr[fm][2] = *(const u32t*)&Ah[cur][r][2 * tg + 8];
            afr[fm][3] = *(const u32t*)&Ah[cur][r + 8][2 * tg + 8];
        }
#pragma unroll
        for (int fn = 0; fn < 8; fn++) {
            int co = wpc + fn * 8 + g;
            u32t bfr[2];
            bfr[0] = *(const u32t*)&Bh[cur][co][2 * tg];
            bfr[1] = *(const u32t*)&Bh[cur][co][2 * tg + 8];
#pragma unroll
            for (int fm = 0; fm < 2; fm++)
                mma16816(acc[fm][fn], afr[fm], bfr);
        }

        if (it + 1 < NT) M_STORE(cur ^ 1);
        __syncthreads();
    }
#undef M_LOAD
#undef M_STORE

    // epilogue: NHWC half2 stores (rows = pixels, cols = cout)
#pragma unroll
    for (int fm = 0; fm < 2; fm++) {
#pragma unroll
        for (int e = 0; e < 2; e++) {
            int pix = n0 + wpr + fm * 16 + g + e * 8;
            int oy  = pix / Win;
            int ox  = pix - oy * Win;
            int po  = (2 * oy + ph) * Wout + (2 * ox + pw);
            __half* dst = outh + ((size_t)b * NpixO + po) * Cout;
#pragma unroll
            for (int fn = 0; fn < 8; fn++) {
                int co = wpc + fn * 8 + 2 * tg;
                float v0 = acc[fm][fn][2 * e]     + bias[co];
                float v1 = acc[fm][fn][2 * e + 1] + bias[co + 1];
                if (RELU) { v0 = fmaxf(v0, 0.f); v1 = fmaxf(v1, 0.f); }
                __half2 h;
                h.x = __float2half_rn(v0);
                h.y = __float2half_rn(v1);
                *(__half2*)(dst + co) = h;
            }
        }
    }
}

// ---------------- dec2: 3x3 conv from NHWC fp16, halo smem -----------------
__global__ void __launch_bounds__(256)
dec2_kernel(const __half* __restrict__ in, const float* __restrict__ w,
            const float* __restrict__ bias, float* __restrict__ out)
{
    __shared__ __half Hs[324 * 66];        // 18x18 halo, pitch 66 halfs
    __shared__ float  wsh[3 * 576];        // [co][q*64+ci] fp32

    const int t  = threadIdx.x;
    const int b  = blockIdx.y;
    const int ty0 = (blockIdx.x >> 4) * 16;
    const int tx0 = (blockIdx.x & 15) * 16;

    for (int i = t; i < 3 * 576; i += 256) {
        int co = i / 576;
        int r  = i % 576;
        int q  = r >> 6;
        int ci = r & 63;
        int kh = q / 3, kw = q % 3;
        wsh[i] = w[((ci * 3 + co) * 3 + (2 - kh)) * 3 + (2 - kw)];
    }

    const __half* inb = in + (size_t)b * 65536 * 64;
    for (int u = t; u < 324 * 8; u += 256) {
        int row = u >> 3;
        int sg  = u & 7;
        int hy  = ty0 - 1 + row / 18;
        int hx  = tx0 - 1 + row % 18;
        uint4 v = make_uint4(0, 0, 0, 0);
        if (hy >= 0 && hy < 256 && hx >= 0 && hx < 256)
            v = *(const uint4*)(inb + ((size_t)(hy * 256 + hx)) * 64 + sg * 8);
        u32t* d = (u32t*)(Hs + row * 66 + sg * 8);
        d[0] = v.x; d[1] = v.y; d[2] = v.z; d[3] = v.w;
    }
    __syncthreads();

    const int ly = t >> 4;
    const int lx = t & 15;
    float a0 = bias[0], a1 = bias[1], a2 = bias[2];
#pragma unroll
    for (int qy = 0; qy < 3; qy++)
#pragma unroll
        for (int qx = 0; qx < 3; qx++) {
            int q = qy * 3 + qx;
            const __half* hrow = Hs + ((ly + qy) * 18 + lx + qx) * 66;
            const float* w0 = wsh + 0 * 576 + q * 64;
            const float* w1 = wsh + 1 * 576 + q * 64;
            const float* w2 = wsh + 2 * 576 + q * 64;
            for (int c2 = 0; c2 < 32; c2++) {
                float2 f = __half22float2(*(const __half2*)(hrow + c2 * 2));
                a0 += f.x * w0[c2 * 2] + f.y * w0[c2 * 2 + 1];
                a1 += f.x * w1[c2 * 2] + f.y * w1[c2 * 2 + 1];
                a2 += f.x * w2[c2 * 2] + f.y * w2[c2 * 2 + 1];
            }
        }
    int oy = ty0 + ly, ox = tx0 + lx;
    int p = oy * 256 + ox;
    out[((size_t)b * 3 + 0) * 65536 + p] = a0;
    out[((size_t)b * 3 + 1) * 65536 + p] = a1;
    out[((size_t)b * 3 + 2) * 65536 + p] = a2;
}

// ------------------------------- VQ (bit-frozen) ---------------------------
__global__ void zero_counts_kernel() { g_counts[threadIdx.x] = 0; }

__global__ void esq_kernel(const float* __restrict__ emb)
{
    int k = blockIdx.x * 128 + threadIdx.x;
    if (k < 512) {
        const float4* e = (const float4*)(emb + (size_t)k * 256);
        float s = 0.f;
#pragma unroll
        for (int i = 0; i < 64; i++) {
            float4 v = e[i];
            s += v.x * v.x + v.y * v.y + v.z * v.z + v.w * v.w;
        }
        g_esq[k] = s;
    }
}

__global__ void __launch_bounds__(256)
vq_kernel(const float* __restrict__ ze, const float* __restrict__ emb,
          float* __restrict__ zq_nhwc, __half* __restrict__ dec_h)
{
    __shared__ u64   Zsd[256][32];
    __shared__ float Es[32][64];
    __shared__ float zpart[32][8];
    __shared__ float zsqs[32];
    __shared__ float rbest[32][16];
    __shared__ int   rk[32][16];
    __shared__ int   fidx[32];

    const int t  = threadIdx.x;
    const int n0 = blockIdx.x * 32;
    const int tm = t >> 4;
    const int tn = t & 15;
    const int r0 = tm * 2, r1 = tm * 2 + 1;

#pragma unroll
    for (int j = 0; j < 8; j++) {
        int idx = t + 256 * j;
        int m   = idx >> 6;
        int kq  = idx & 63;
        float4 v = *(const float4*)(ze + ((size_t)(n0 + m)) * 256 + kq * 4);
        Zsd[kq * 4 + 0][m] = dup2(v.x); Zsd[kq * 4 + 1][m] = dup2(v.y);
        Zsd[kq * 4 + 2][m] = dup2(v.z); Zsd[kq * 4 + 3][m] = dup2(v.w);
    }
    __syncthreads();

    {
        int row = t & 31;
        int seg = t >> 5;
        float s = 0.f;
#pragma unroll
        for (int i = 0; i < 32; i++) {
            float v = ((const float*)&Zsd[seg * 32 + i][row])[0];
            s += v * v;
        }
        zpart[row][seg] = s;
    }
    __syncthreads();
    if (t < 32) {
        float s = zpart[t][0];
#pragma unroll
        for (int q = 1; q < 8; q++) s += zpart[t][q];
        zsqs[t] = s;
    }
    __syncthreads();

    const float zr0 = zsqs[r0];
    const float zr1 = zsqs[r1];

    float best[2] = {1e30f, 1e30f};
    int   bk[2]   = {0, 0};

    for (int e0 = 0; e0 < 512; e0 += 64) {
        u64 accP[8][2][2];
#pragma unroll
        for (int l = 0; l < 8; l++)
#pragma unroll
            for (int i = 0; i < 2; i++)
#pragma unroll
                for (int cp = 0; cp < 2; cp++) accP[l][i][cp] = 0ull;

        for (int kb = 0; kb < 256; kb += 32) {
            __syncthreads();
#pragma unroll
            for (int j = 0; j < 2; j++) {
                int idx = t + 256 * j;
                int e   = idx >> 3;
                int k4  = (idx & 7) * 4;
                float4 v = *(const float4*)(emb + (size_t)(e0 + e) * 256 + kb + k4);
                Es[k4 + 0][e] = v.x; Es[k4 + 1][e] = v.y;
                Es[k4 + 2][e] = v.z; Es[k4 + 3][e] = v.w;
            }
            __syncthreads();
#pragma unroll
            for (int k = 0; k < 32; k++) {
                const int l = k & 7;
                u64 A0 = Zsd[kb + k][r0];
                u64 A1 = Zsd[kb + k][r1];
                ulonglong2 B = *(const ulonglong2*)&Es[k][tn * 4];
                ffma2(accP[l][0][0], A0, B.x);
                ffma2(accP[l][0][1], A0, B.y);
                ffma2(accP[l][1][0], A1, B.x);
                ffma2(accP[l][1][1], A1, B.y);
            }
        }
#pragma unroll
        for (int i = 0; i < 2; i++) {
            float zr = (i == 0) ? zr0 : zr1;
#pragma unroll
            for (int cp = 0; cp < 2; cp++) {
                float v0[8], v1[8];
#pragma unroll
                for (int l = 0; l < 8; l++) unpack2(accP[l][i][cp], v0[l], v1[l]);
                {
                    float q0 = __fadd_rn(v0[0], v0[4]);
                    float q1 = __fadd_rn(v0[1], v0[5]);
                    float q2 = __fadd_rn(v0[2], v0[6]);
                    float q3 = __fadd_rn(v0[3], v0[7]);
                    float d  = __fadd_rn(__fadd_rn(q0, q2), __fadd_rn(q1, q3));
                    int kcode = e0 + tn * 4 + 2 * cp;
                    float eq = g_esq[kcode];
                    float s = __fadd_rn(__fadd_rn(zr, eq), -__fmul_rn(2.f, d));
                    if (s < best[i]) { best[i] = s; bk[i] = kcode; }
                }
                {
                    float q0 = __fadd_rn(v1[0], v1[4]);
                    float q1 = __fadd_rn(v1[1], v1[5]);
                    float q2 = __fadd_rn(v1[2], v1[6]);
                    float q3 = __fadd_rn(v1[3], v1[7]);
                    float d  = __fadd_rn(__fadd_rn(q0, q2), __fadd_rn(q1, q3));
                    int kcode = e0 + tn * 4 + 2 * cp + 1;
                    float eq = g_esq[kcode];
                    float s = __fadd_rn(__fadd_rn(zr, eq), -__fmul_rn(2.f, d));
                    if (s < best[i]) { best[i] = s; bk[i] = kcode; }
                }
            }
        }
    }
    __syncthreads();
    rbest[r0][tn] = best[0]; rk[r0][tn] = bk[0];
    rbest[r1][tn] = best[1]; rk[r1][tn] = bk[1];
    __syncthreads();
    if (t < 32) {
        float bs = rbest[t][0];
        int   bi = rk[t][0];
#pragma unroll
        for (int q = 1; q < 16; q++) {
            float s = rbest[t][q];
            int   k = rk[t][q];
            if (s < bs || (s == bs && k < bi)) { bs = s; bi = k; }
        }
        fidx[t] = bi;
        atomicAdd(&g_counts[bi], 1);
    }
    __syncthreads();

    // z_q NHWC fp32 (exact codebook rows)
#pragma unroll
    for (int j = 0; j < 8; j++) {
        int idx = t + 256 * j;
        int m   = idx >> 6;
        int d4  = idx & 63;
        float4 v = *(const float4*)(emb + (size_t)fidx[m] * 256 + d4 * 4);
        *(float4*)(zq_nhwc + ((size_t)(n0 + m)) * 256 + d4 * 4) = v;
    }
    // dec_in NHWC fp16: z_e + (z_q - z_e)
#pragma unroll
    for (int j = 0; j < 16; j++) {
        int u   = t + 256 * j;
        int m   = u >> 7;
        int d   = (u & 127) * 2;
        int n   = n0 + m;
        int code = fidx[m];
        float2 qv = *(const float2*)(emb + (size_t)code * 256 + d);
        float2 zv = *(const float2*)(ze + (size_t)n * 256 + d);
        float d0 = zv.x + (qv.x - zv.x);
        float d1 = zv.y + (qv.y - zv.y);
        __half2 h;
        h.x = __float2half_rn(d0);
        h.y = __float2half_rn(d1);
        *(__half2*)(dec_h + (size_t)n * 256 + d) = h;
    }
}

__global__ void perp_kernel(float* __restrict__ out)
{
    __shared__ float red[512];
    int t = threadIdx.x;
    float p = (float)g_counts[t] * (1.f / 65536.f);
    red[t] = p * logf(p + 1e-10f);
    __syncthreads();
    for (int s = 256; s > 0; s >>= 1) {
        if (t < s) red[t] += red[t + s];
        __syncthreads();
    }
    if (t == 0) out[0] = expf(-red[0]);
}

// ---------------------------------------------------------------------------
extern "C" void kernel_launch(void* const* d_in, const int* in_sizes, int n_in,
                              void* d_out, int out_size)
{
    const float* x      = (const float*)d_in[0];
    const float* w_enc1 = (const float*)d_in[1];
    const float* b_enc1 = (const float*)d_in[2];
    const float* w_enc2 = (const float*)d_in[3];
    const float* b_enc2 = (const float*)d_in[4];
    const float* w_prevq= (const float*)d_in[5];
    const float* b_prevq= (const float*)d_in[6];
    const float* emb    = (const float*)d_in[7];
    const float* w_post = (const float*)d_in[8];
    const float* b_post = (const float*)d_in[9];
    const float* w_dec1 = (const float*)d_in[10];
    const float* b_dec1 = (const float*)d_in[11];
    const float* w_dec2 = (const float*)d_in[12];
    const float* b_dec2 = (const float*)d_in[13];

    float* out  = (float*)d_out;
    float* ze   = out + OFF_ZE;
    float* zq   = out + OFF_ZQ;
    float* perp = out + OFF_PERP;

    void* p;
    cudaGetSymbolAddress(&p, g_h1);        float*  h1   = (float*)p;
    cudaGetSymbolAddress(&p, g_h2);        float*  h2   = (float*)p;
    cudaGetSymbolAddress(&p, g_zq_h);      __half* zqh  = (__half*)p;
    cudaGetSymbolAddress(&p, g_d1h);       __half* d1h  = (__half*)p;
    cudaGetSymbolAddress(&p, g_d2h);       __half* d2h  = (__half*)p;
    cudaGetSymbolAddress(&p, g_wt2_post);  __half* wtp  = (__half*)p;
    cudaGetSymbolAddress(&p, g_wt2_dec1);  __half* wtd  = (__half*)p;
    cudaGetSymbolAddress(&p, g_wc1);       float*  wc1  = (float*)p;
    cudaGetSymbolAddress(&p, g_wc2);       float*  wc2  = (float*)p;
    cudaGetSymbolAddress(&p, g_wc3);       float*  wc3  = (float*)p;

    zero_counts_kernel<<<1, 512>>>();
    esq_kernel<<<4, 128>>>(emb);
    repack_conv<3, 64, 4><<<12, 256>>>(w_enc1, wc1);
    repack_conv<64, 128, 4><<<512, 256>>>(w_enc2, wc2);
    repack_conv<128, 256, 3><<<1152, 256>>>(w_prevq, wc3);
    repack_t05<256, 128><<<2048, 256>>>(w_post, wtp);
    repack_t05<128, 64><<<512, 256>>>(w_dec1, wtd);

    // encoder (bit-frozen)
    conv_gemm<3, 64, 4, 2, 1, 256, 256, 128, 128, true, false>
        <<<dim3(256, 1, 16), 256>>>(x, wc1, b_enc1, h1);
    conv_gemm2<64, 128, 4, 2, 1, 128, 128, 64, 64, true, false>
        <<<dim3(32, 1, 16), 256>>>(h1, wc2, b_enc2, h2);
    conv_gemm2<128, 256, 3, 1, 1, 64, 64, 64, 64, false, true>
        <<<dim3(32, 2, 16), 256>>>(h2, wc3, b_prevq, ze);

    vq_kernel<<<2048, 256>>>(ze, emb, zq, zqh);
    perp_kernel<<<1, 512>>>(perp);

    // decoder (mma.sync fp16, NHWC)
    tconv_mma<256, 128, 64, 64, false, 128>
        <<<dim3(32, 4, 16), 256>>>(zqh, wtp, b_post, d1h);
    tconv_mma<128, 64, 128, 128, true, 256>
        <<<dim3(64, 4, 16), 256>>>(d1h, wtd, b_dec1, d2h);
    dec2_kernel<<<dim3(256, 16), 256>>>(d2h, w_dec2, b_dec2, out);
}